// round 12
// baseline (speedup 1.0000x reference)
#include <cuda_runtime.h>
#include <cuda_fp16.h>
#include <math.h>
#include <stdint.h>

// ---------------- problem dims ----------------
#define M_TOK 4096
#define D_IN  1024
#define N_EXP 16
#define P_SLOT 1024
#define H_HID 1365
#define H_PAD 1408
#define NP    16384

// ---------------- scratch (all GEMM operands plain fp16) ----------------
__device__ __half g_Ch [(size_t)M_TOK*NP];          // logits (fp16) then combine weights, in place
__device__ __half g_Dh [(size_t)M_TOK*NP];          // dispatch weights [m, np] (consumed MN-major)
__device__ __half g_xf [(size_t)M_TOK*D_IN];        // x fp16 [m, d]
__device__ __half g_xT [(size_t)D_IN*M_TOK];        // x transposed [d, m]
__device__ __half g_phiT[(size_t)NP*D_IN];          // phi transposed [np, d]
__device__ __half g_W1T [(size_t)N_EXP*H_HID*D_IN]; // [n][h, d]
__device__ __half g_W2T [(size_t)N_EXP*P_SLOT*H_PAD]; // [n][o, h_pad] (pad zeroed)
__device__ __half g_Xs  [(size_t)NP*D_IN];          // slot inputs [np, d]
__device__ __half g_H   [(size_t)N_EXP*P_SLOT*H_PAD]; // hidden [n][p, h_pad] (pad zeroed)
__device__ __half g_YsT [(size_t)P_SLOT*NP];        // slot outputs transposed [o, np]

// ---------------- helpers ----------------
__device__ __forceinline__ uint32_t smem_u32(const void* p) {
    return (uint32_t)__cvta_generic_to_shared(p);
}
#define SWZ(x)    ((x) ^ (((x) >> 3) & 0x70))   // 128B-row swizzle
#define SWZ256(x) ((x) ^ (((x) >> 4) & 0xF0))   // 256B-row swizzle (A-trans tiles)

__device__ __forceinline__ void ldsm_x4(uint32_t* r, uint32_t addr) {
    asm volatile("ldmatrix.sync.aligned.m8n8.x4.shared.b16 {%0,%1,%2,%3}, [%4];"
                 : "=r"(r[0]), "=r"(r[1]), "=r"(r[2]), "=r"(r[3]) : "r"(addr));
}
__device__ __forceinline__ void ldsm_x4_t(uint32_t* r, uint32_t addr) {
    asm volatile("ldmatrix.sync.aligned.m8n8.x4.trans.shared.b16 {%0,%1,%2,%3}, [%4];"
                 : "=r"(r[0]), "=r"(r[1]), "=r"(r[2]), "=r"(r[3]) : "r"(addr));
}
__device__ __forceinline__ void mma16816(float* c, const uint32_t* a, const uint32_t* b) {
    asm volatile("mma.sync.aligned.m16n8k16.row.col.f32.f16.f16.f32 "
        "{%0,%1,%2,%3}, {%4,%5,%6,%7}, {%8,%9}, {%0,%1,%2,%3};"
        : "+f"(c[0]), "+f"(c[1]), "+f"(c[2]), "+f"(c[3])
        : "r"(a[0]), "r"(a[1]), "r"(a[2]), "r"(a[3]), "r"(b[0]), "r"(b[1]));
}
__device__ __forceinline__ void cp16(uint32_t dst, const void* src, int srcsize) {
    asm volatile("cp.async.cg.shared.global [%0], [%1], 16, %2;"
                 :: "r"(dst), "l"(src), "r"(srcsize) : "memory");
}
#define CP_COMMIT() asm volatile("cp.async.commit_group;" ::: "memory")
#define CP_WAIT(n)  asm volatile("cp.async.wait_group %0;" :: "n"(n) : "memory")

// smem: 2 stages x (A 16KB + B 16KB)
#define STG_BYTES  32768
#define SMEM_GEMM  (2 * STG_BYTES)

// ---------------------------------------------------------------------------
// fp16 HMMA GEMM: D[128,128] = A * B[N,K]^T
//  ATR=false: A is [M,K] K-major (ldA = row length)
//  ATR=true : A is [K,M] MN-major (ldA = row length in m); tile stored as
//             64 k-rows x 256B, fragments via ldmatrix.trans (bit-identical math)
// CTA 128x128, EIGHT warps each 64x32 (4 warps/SMSP at occ 2 for latency cover).
// EPI: 0 = fp32 row-major (ldOut)
//      1 = fp16 row-major (ldOut)
//      2 = fp16 row-major + bias[col] + relu + zero-pad cols >= outN
//      4 = fp16 row-major + bias[row], batch column offset z*outBatch
// ---------------------------------------------------------------------------
template<int EPI, bool BCHECK, bool ATR>
__global__ __launch_bounds__(256, 2)
void gemm_f16(const __half* __restrict__ A, const __half* __restrict__ B,
              const float* __restrict__ bias, void* __restrict__ outp,
              int K, int Nrows, int ldA, int ldB,
              long sA, long sB, long sBias, long outBatch,
              int ldOut, int outN)
{
    extern __shared__ char smraw[];
    const uint32_t smb = smem_u32(smraw);
    const int tid = threadIdx.x, wid = tid >> 5, lane = tid & 31;
    const int z  = blockIdx.z;
    const int m0 = blockIdx.x * 128, n0 = blockIdx.y * 128;
    A += (long)z * sA;
    B += (long)z * sB;
    const float* biasp = bias ? (bias + (long)z * sBias) : bias;

    const int nCh = K >> 6;           // K chunks of 64 fp16
    const int lrow = tid >> 3;        // 0..31
    const int lj   = tid & 7;         // 16B lane within 128B row

    auto issue = [&](int c) {
        const uint32_t smA = smb + (c & 1) * STG_BYTES;
        const uint32_t smB = smA + 16384;
        const long kb = (long)c * 64 + lj * 8;   // fp16 element offset (K-major use)
        if (ATR) {
            // A tile: 64 k-rows x 128 m-cols (256B rows), from A[K,M] rows c*64..+64
            const int lrow2 = tid >> 4;          // 0..15
            const int lj2   = tid & 15;          // 16B chunk within 256B row
            #pragma unroll
            for (int i = 0; i < 4; ++i) {
                int r = lrow2 + i * 16;          // k-row within chunk
                cp16(smA + SWZ256(r * 256 + lj2 * 16),
                     A + (long)(c * 64 + r) * ldA + (m0 + lj2 * 8), 16);
            }
        } else {
            #pragma unroll
            for (int i = 0; i < 4; ++i) {
                int r = lrow + i * 32;
                cp16(smA + SWZ(r * 128 + lj * 16), A + (long)(m0 + r) * ldA + kb, 16);
            }
        }
        #pragma unroll
        for (int i = 0; i < 4; ++i) {
            int r = lrow + i * 32;
            int ok = (!BCHECK) || (n0 + r) < Nrows;
            const __half* src = B + (long)(ok ? (n0 + r) : 0) * ldB + kb;
            cp16(smB + SWZ(r * 128 + lj * 16), src, ok ? 16 : 0);
        }
        CP_COMMIT();
    };

    float acc[4][4][4] = {};                 // [mb][nb][c0..c3]
    const int wm = (wid >> 2) * 64;          // warp m offset (0/64)
    const int wn = (wid & 3) * 32;           // warp n offset (0/32/64/96)

    issue(0);

    for (int c = 0; c < nCh; ++c) {
        if (c + 1 < nCh) { issue(c + 1); CP_WAIT(1); } else { CP_WAIT(0); }
        __syncthreads();

        const uint32_t smA = smb + (c & 1) * STG_BYTES;
        const uint32_t smB = smA + 16384;

        #pragma unroll
        for (int ks = 0; ks < 4; ++ks) {
            const int kb = ks * 32;          // byte offset of k16 within 128B row
            uint32_t af[4][4], bf[4][2];
            if (ATR) {
                // trans fragments: row = k, col = m; 8x8 blocks per PTX A-frag order
                const int krow = ks * 16 + (lane & 7) + ((lane >> 4) << 3);
                const int msub = ((lane >> 3) & 1) << 3;
                #pragma unroll
                for (int mb = 0; mb < 4; ++mb) {
                    int mcol = wm + mb * 16 + msub;
                    ldsm_x4_t(af[mb], smA + SWZ256(krow * 256 + mcol * 2));
                }
            } else {
                #pragma unroll
                for (int mb = 0; mb < 4; ++mb) {
                    int row = wm + mb * 16 + (lane & 15);
                    ldsm_x4(af[mb], smA + SWZ(row * 128 + kb + ((lane >> 4) << 4)));
                }
            }
            #pragma unroll
            for (int npair = 0; npair < 2; ++npair) {
                int row = wn + npair * 16 + (lane & 7) + ((lane >> 4) << 3);
                uint32_t r4[4];
                ldsm_x4(r4, smB + SWZ(row * 128 + kb + (((lane >> 3) & 1) << 4)));
                bf[npair*2  ][0] = r4[0]; bf[npair*2  ][1] = r4[1];
                bf[npair*2+1][0] = r4[2]; bf[npair*2+1][1] = r4[3];
            }
            #pragma unroll
            for (int mb = 0; mb < 4; ++mb)
                #pragma unroll
                for (int nb = 0; nb < 4; ++nb)
                    mma16816(acc[mb][nb], af[mb], bf[nb]);
        }
        __syncthreads();
    }

    // ---------------- epilogue (all variants coalesced) ----------------
    const int erow = lane >> 2;
    const int ecol = (lane & 3) * 2;
    #pragma unroll
    for (int mb = 0; mb < 4; ++mb) {
        #pragma unroll
        for (int nb = 0; nb < 4; ++nb) {
            float* cc = acc[mb][nb];
            const int gm = m0 + wm + mb * 16 + erow;
            const int gc = n0 + wn + nb * 8 + ecol;
            if (EPI == 0) {
                *(float2*)((float*)outp + (long)gm * ldOut + gc)       = make_float2(cc[0], cc[1]);
                *(float2*)((float*)outp + (long)(gm + 8) * ldOut + gc) = make_float2(cc[2], cc[3]);
            } else if (EPI == 4) {
                __half* ob = (__half*)outp + (long)z * outBatch;   // column offset per expert
                #pragma unroll
                for (int h = 0; h < 2; ++h) {
                    int gmm = gm + h * 8;
                    float bv = biasp[gmm];
                    __half2 hv = __floats2half2_rn(cc[h * 2] + bv, cc[h * 2 + 1] + bv);
                    *(__half2*)(ob + (long)gmm * ldOut + gc) = hv;
                }
            } else {
                __half* ob = (__half*)outp + (long)z * outBatch;
                #pragma unroll
                for (int h = 0; h < 2; ++h) {
                    int gmm = gm + h * 8;
                    float v0 = cc[h * 2], v1 = cc[h * 2 + 1];
                    if (EPI == 2) {
                        v0 = (gc     < outN) ? fmaxf(v0 + biasp[gc],     0.0f) : 0.0f;
                        v1 = (gc + 1 < outN) ? fmaxf(v1 + biasp[gc + 1], 0.0f) : 0.0f;
                    }
                    __half2 hv = __floats2half2_rn(v0, v1);
                    *(__half2*)(ob + (long)gmm * ldOut + gc) = hv;
                }
            }
        }
    }
}

// ---------------------------------------------------------------------------
// elementwise convert fp32 -> fp16
// ---------------------------------------------------------------------------
__global__ __launch_bounds__(256) void convert_f16(const float* __restrict__ in,
                                                   __half* __restrict__ out, long total)
{
    for (long idx = blockIdx.x * 256L + threadIdx.x; idx < total; idx += (long)gridDim.x * 256)
        out[idx] = __float2half(in[idx]);
}

// ---------------------------------------------------------------------------
// transpose+convert: fp32 in[R,Cc] -> fp16 out[Cc, segK], out[c][k]=in[k][c] (k<R else 0)
// ---------------------------------------------------------------------------
__global__ __launch_bounds__(256) void transpose_f32(const float* __restrict__ in,
                                                     __half* __restrict__ out,
                                                     int R, int Cc, int segK,
                                                     long inBatch, long outBatch)
{
    __shared__ float t[32][33];
    const int z = blockIdx.z;
    in  += (long)z * inBatch;
    out += (long)z * outBatch;
    const int c0 = blockIdx.x * 32, k0 = blockIdx.y * 32;
    const int tx = threadIdx.x, ty = threadIdx.y;   // 32 x 8

    #pragma unroll
    for (int i = 0; i < 4; ++i) {
        int k = k0 + ty + i * 8, c = c0 + tx;
        float v = 0.0f;
        if (k < R && c < Cc) v = in[(long)k * Cc + c];
        t[ty + i * 8][tx] = v;
    }
    __syncthreads();
    #pragma unroll
    for (int i = 0; i < 4; ++i) {
        int c = c0 + ty + i * 8, k = k0 + tx;
        if (c < Cc && k < segK)
            out[(long)c * segK + k] = __float2half(t[tx][ty + i * 8]);
    }
}

// ---------------------------------------------------------------------------
// softmax: per token m, from fp16 logits. Ch (may alias logits) [m,NP], Dh [m,NP]
// ---------------------------------------------------------------------------
__global__ __launch_bounds__(256) void softmax_kernel(const __half* __restrict__ logits,
                                                      __half* __restrict__ Ch,
                                                      __half* __restrict__ Dh)
{
    extern __shared__ float row[];               // 16384 floats
    __shared__ float red[256];
    const int m = blockIdx.x, tid = threadIdx.x;
    const __half* lrow = logits + (size_t)m * NP;

    float mx = -INFINITY;
    for (int i = tid; i < NP; i += 256) { float v = __half2float(lrow[i]); row[i] = v; mx = fmaxf(mx, v); }
    red[tid] = mx; __syncthreads();
    for (int s = 128; s > 0; s >>= 1) { if (tid < s) red[tid] = fmaxf(red[tid], red[tid + s]); __syncthreads(); }
    mx = red[0]; __syncthreads();

    float sum = 0.0f;
    for (int i = tid; i < NP; i += 256) sum += expf(row[i] - mx);
    red[tid] = sum; __syncthreads();
    for (int s = 128; s > 0; s >>= 1) { if (tid < s) red[tid] += red[tid + s]; __syncthreads(); }
    const float inv = 1.0f / red[0];

    __half* crow = Ch + (size_t)m * NP;
    for (int i = tid; i < NP; i += 256)
        crow[i] = __float2half(expf(row[i] - mx) * inv);

    __half* drow = Dh + (size_t)m * NP;
    for (int p = tid; p < P_SLOT; p += 256) {
        float l[N_EXP], mn = -INFINITY;
        #pragma unroll
        for (int n = 0; n < N_EXP; n++) { l[n] = row[n * P_SLOT + p]; mn = fmaxf(mn, l[n]); }
        float s2 = 0.0f;
        #pragma unroll
        for (int n = 0; n < N_EXP; n++) { l[n] = expf(l[n] - mn); s2 += l[n]; }
        const float inv2 = 1.0f / s2;
        #pragma unroll
        for (int n = 0; n < N_EXP; n++) drow[n * P_SLOT + p] = __float2half(l[n] * inv2);
    }
}

// ---------------------------------------------------------------------------
extern "C" void kernel_launch(void* const* d_in, const int* in_sizes, int n_in,
                              void* d_out, int out_size)
{
    const float* x   = (const float*)d_in[0];
    const float* phi = (const float*)d_in[1];
    const float* W1  = (const float*)d_in[2];
    const float* b1  = (const float*)d_in[3];
    const float* W2  = (const float*)d_in[4];
    const float* b2  = (const float*)d_in[5];
    float* out = (float*)d_out;

    __half *Ch, *Dh, *xf, *xT, *phiT, *W1T, *W2T, *Xs, *H, *YsT;
    cudaGetSymbolAddress((void**)&Ch,   g_Ch);
    cudaGetSymbolAddress((void**)&Dh,   g_Dh);
    cudaGetSymbolAddress((void**)&xf,   g_xf);
    cudaGetSymbolAddress((void**)&xT,   g_xT);
    cudaGetSymbolAddress((void**)&phiT, g_phiT);
    cudaGetSymbolAddress((void**)&W1T,  g_W1T);
    cudaGetSymbolAddress((void**)&W2T,  g_W2T);
    cudaGetSymbolAddress((void**)&Xs,   g_Xs);
    cudaGetSymbolAddress((void**)&H,    g_H);
    cudaGetSymbolAddress((void**)&YsT,  g_YsT);

    cudaFuncSetAttribute(gemm_f16<0,false,false>, cudaFuncAttributeMaxDynamicSharedMemorySize, SMEM_GEMM);
    cudaFuncSetAttribute(gemm_f16<1,false,false>, cudaFuncAttributeMaxDynamicSharedMemorySize, SMEM_GEMM);
    cudaFuncSetAttribute(gemm_f16<1,false,true>,  cudaFuncAttributeMaxDynamicSharedMemorySize, SMEM_GEMM);
    cudaFuncSetAttribute(gemm_f16<2,true,false>,  cudaFuncAttributeMaxDynamicSharedMemorySize, SMEM_GEMM);
    cudaFuncSetAttribute(gemm_f16<4,false,false>, cudaFuncAttributeMaxDynamicSharedMemorySize, SMEM_GEMM);
    cudaFuncSetAttribute(softmax_kernel,          cudaFuncAttributeMaxDynamicSharedMemorySize, NP * 4);

    dim3 t256(256), t32x8(32, 8);

    // operand prep
    convert_f16<<<2048, t256>>>(x, xf, (long)M_TOK * D_IN);
    transpose_f32<<<dim3(NP/32, D_IN/32, 1),    t32x8>>>(phi, phiT, D_IN, NP, D_IN, 0, 0);
    transpose_f32<<<dim3(D_IN/32, M_TOK/32, 1), t32x8>>>(x, xT, M_TOK, D_IN, M_TOK, 0, 0);
    transpose_f32<<<dim3(43, D_IN/32, N_EXP),   t32x8>>>(W1, W1T, D_IN, H_HID, D_IN,
                                                 (long)D_IN*H_HID, (long)H_HID*D_IN);
    transpose_f32<<<dim3(P_SLOT/32, 44, N_EXP), t32x8>>>(W2, W2T, H_HID, P_SLOT, H_PAD,
                                                 (long)H_HID*P_SLOT, (long)P_SLOT*H_PAD);

    // 1) logits(fp16, into Ch) = x @ phi   (M=4096, N=16384, K=1024)
    gemm_f16<1,false,false><<<dim3(M_TOK/128, NP/128), t256, SMEM_GEMM>>>(
        xf, phiT, nullptr, Ch, D_IN, NP, D_IN, D_IN, 0,0,0,0, NP, 0);

    // 2) softmaxes: Ch (in place), Dh
    softmax_kernel<<<M_TOK, t256, NP*4>>>(Ch, Ch, Dh);

    // 3) Xs = D^T @ x  via A-trans directly on Dh (M=16384 slots, N=1024, K=4096 tokens)
    gemm_f16<1,false,true><<<dim3(NP/128, D_IN/128), t256, SMEM_GEMM>>>(
        Dh, xT, nullptr, Xs, M_TOK, D_IN, NP, M_TOK, 0,0,0,0, D_IN, 0);

    // 4) H = relu(Xs @ W1 + b1)  per expert (M=1024, N=1365->1408, K=1024)
    gemm_f16<2,true,false><<<dim3(P_SLOT/128, 11, N_EXP), t256, SMEM_GEMM>>>(
        Xs, W1T, b1, H, D_IN, H_HID, D_IN, D_IN,
        (long)P_SLOT*D_IN, (long)H_HID*D_IN, H_HID, (long)P_SLOT*H_PAD, H_PAD, H_HID);

    // 5) YsT[o, n*1024+p] = W2T[n] @ H[n]^T + b2[o]  (M=1024 o, N=1024 p, K=1408)
    gemm_f16<4,false,false><<<dim3(P_SLOT/128, P_SLOT/128, N_EXP), t256, SMEM_GEMM>>>(
        W2T, H, b2, YsT, H_PAD, P_SLOT, H_PAD, H_PAD,
        (long)P_SLOT*H_PAD, (long)P_SLOT*H_PAD, P_SLOT, P_SLOT, NP, 0);

    // 6) Y = C @ Ys^T  (M=4096, N=1024, K=16384) -> fp32
    gemm_f16<0,false,false><<<dim3(M_TOK/128, D_IN/128), t256, SMEM_GEMM>>>(
        Ch, YsT, nullptr, out, NP, D_IN, NP, NP, 0,0,0,0, D_IN, 0);

    (void)in_sizes; (void)n_in; (void)out_size;
}

// round 13
// speedup vs baseline: 1.0089x; 1.0089x over previous
#include <cuda_runtime.h>
#include <cuda_fp16.h>
#include <math.h>
#include <stdint.h>

// ---------------- problem dims ----------------
#define M_TOK 4096
#define D_IN  1024
#define N_EXP 16
#define P_SLOT 1024
#define H_HID 1365
#define H_PAD 1408
#define NP    16384
#define SPLITK 4

// ---------------- scratch ----------------
__device__ __half g_Ch [(size_t)M_TOK*NP];          // logits (fp16) then combine weights, in place
__device__ __half g_Dh [(size_t)M_TOK*NP];          // dispatch weights [m, np] (consumed MN-major)
__device__ __half g_xf [(size_t)M_TOK*D_IN];        // x fp16 [m, d]
__device__ __half g_xT [(size_t)D_IN*M_TOK];        // x transposed [d, m]
__device__ __half g_phiT[(size_t)NP*D_IN];          // phi transposed [np, d]
__device__ __half g_W1T [(size_t)N_EXP*H_HID*D_IN]; // [n][h, d]
__device__ __half g_W2T [(size_t)N_EXP*P_SLOT*H_PAD]; // [n][o, h_pad] (pad zeroed)
__device__ __half g_Xs  [(size_t)NP*D_IN];          // slot inputs [np, d]
__device__ __half g_H   [(size_t)N_EXP*P_SLOT*H_PAD]; // hidden [n][p, h_pad] (pad zeroed)
__device__ __half g_YsT [(size_t)P_SLOT*NP];        // slot outputs transposed [o, np]
__device__ float  g_Yp [(size_t)SPLITK*M_TOK*D_IN]; // combine split-K partials (fp32)

// ---------------- helpers ----------------
__device__ __forceinline__ uint32_t smem_u32(const void* p) {
    return (uint32_t)__cvta_generic_to_shared(p);
}
#define SWZ(x)    ((x) ^ (((x) >> 3) & 0x70))   // 128B-row swizzle
#define SWZ256(x) ((x) ^ (((x) >> 4) & 0xF0))   // 256B-row swizzle (A-trans tiles)

__device__ __forceinline__ void ldsm_x4(uint32_t* r, uint32_t addr) {
    asm volatile("ldmatrix.sync.aligned.m8n8.x4.shared.b16 {%0,%1,%2,%3}, [%4];"
                 : "=r"(r[0]), "=r"(r[1]), "=r"(r[2]), "=r"(r[3]) : "r"(addr));
}
__device__ __forceinline__ void ldsm_x4_t(uint32_t* r, uint32_t addr) {
    asm volatile("ldmatrix.sync.aligned.m8n8.x4.trans.shared.b16 {%0,%1,%2,%3}, [%4];"
                 : "=r"(r[0]), "=r"(r[1]), "=r"(r[2]), "=r"(r[3]) : "r"(addr));
}
__device__ __forceinline__ void mma16816(float* c, const uint32_t* a, const uint32_t* b) {
    asm volatile("mma.sync.aligned.m16n8k16.row.col.f32.f16.f16.f32 "
        "{%0,%1,%2,%3}, {%4,%5,%6,%7}, {%8,%9}, {%0,%1,%2,%3};"
        : "+f"(c[0]), "+f"(c[1]), "+f"(c[2]), "+f"(c[3])
        : "r"(a[0]), "r"(a[1]), "r"(a[2]), "r"(a[3]), "r"(b[0]), "r"(b[1]));
}
__device__ __forceinline__ void cp16(uint32_t dst, const void* src, int srcsize) {
    asm volatile("cp.async.cg.shared.global [%0], [%1], 16, %2;"
                 :: "r"(dst), "l"(src), "r"(srcsize) : "memory");
}
#define CP_COMMIT() asm volatile("cp.async.commit_group;" ::: "memory")
#define CP_WAIT(n)  asm volatile("cp.async.wait_group %0;" :: "n"(n) : "memory")

// smem: 2 stages x (A 16KB + B 16KB)
#define STG_BYTES  32768
#define SMEM_GEMM  (2 * STG_BYTES)

// ---------------------------------------------------------------------------
// fp16 HMMA GEMM (R11-proven engine): D[128,128] = A * B[N,K]^T
//  ATR=false: A is [M,K] K-major; ATR=true: A is [K,M] MN-major via ldmatrix.trans
// CTA 128x128, 4 warps each 64x64, 2-stage cp.async, launch_bounds(128,2).
// EPI: 0 = fp32 row-major (ldOut) at z*outBatch offset (split-K partials)
//      1 = fp16 row-major (ldOut)
//      2 = fp16 row-major + bias[col] + relu + zero-pad cols >= outN
//      4 = fp16 row-major + bias[row], batch column offset z*outBatch
// ---------------------------------------------------------------------------
template<int EPI, bool BCHECK, bool ATR>
__global__ __launch_bounds__(128, 2)
void gemm_f16(const __half* __restrict__ A, const __half* __restrict__ B,
              const float* __restrict__ bias, void* __restrict__ outp,
              int K, int Nrows, int ldA, int ldB,
              long sA, long sB, long sBias, long outBatch,
              int ldOut, int outN)
{
    extern __shared__ char smraw[];
    const uint32_t smb = smem_u32(smraw);
    const int tid = threadIdx.x, wid = tid >> 5, lane = tid & 31;
    const int z  = blockIdx.z;
    const int m0 = blockIdx.x * 128, n0 = blockIdx.y * 128;
    A += (long)z * sA;
    B += (long)z * sB;
    const float* biasp = bias ? (bias + (long)z * sBias) : bias;

    const int nCh = K >> 6;           // K chunks of 64 fp16
    const int lrow = tid >> 3;        // 0..15
    const int lj   = tid & 7;         // 16B lane within 128B row

    auto issue = [&](int c) {
        const uint32_t smA = smb + (c & 1) * STG_BYTES;
        const uint32_t smB = smA + 16384;
        const long kb = (long)c * 64 + lj * 8;
        if (ATR) {
            const int lrow2 = tid >> 4;          // 0..7
            const int lj2   = tid & 15;          // 16B chunk within 256B row
            #pragma unroll
            for (int i = 0; i < 8; ++i) {
                int r = lrow2 + i * 8;
                cp16(smA + SWZ256(r * 256 + lj2 * 16),
                     A + (long)(c * 64 + r) * ldA + (m0 + lj2 * 8), 16);
            }
        } else {
            #pragma unroll
            for (int i = 0; i < 8; ++i) {
                int r = lrow + i * 16;
                cp16(smA + SWZ(r * 128 + lj * 16), A + (long)(m0 + r) * ldA + kb, 16);
            }
        }
        #pragma unroll
        for (int i = 0; i < 8; ++i) {
            int r = lrow + i * 16;
            int ok = (!BCHECK) || (n0 + r) < Nrows;
            const __half* src = B + (long)(ok ? (n0 + r) : 0) * ldB + kb;
            cp16(smB + SWZ(r * 128 + lj * 16), src, ok ? 16 : 0);
        }
        CP_COMMIT();
    };

    float acc[4][8][4] = {};                 // [mb][nb][c0..c3]
    const int wm = (wid >> 1) * 64;
    const int wn = (wid & 1) * 64;

    issue(0);

    for (int c = 0; c < nCh; ++c) {
        if (c + 1 < nCh) { issue(c + 1); CP_WAIT(1); } else { CP_WAIT(0); }
        __syncthreads();

        const uint32_t smA = smb + (c & 1) * STG_BYTES;
        const uint32_t smB = smA + 16384;

        #pragma unroll
        for (int ks = 0; ks < 4; ++ks) {
            const int kb = ks * 32;
            uint32_t af[4][4], bf[8][2];
            if (ATR) {
                const int krow = ks * 16 + (lane & 7) + ((lane >> 4) << 3);
                const int msub = ((lane >> 3) & 1) << 3;
                #pragma unroll
                for (int mb = 0; mb < 4; ++mb) {
                    int mcol = wm + mb * 16 + msub;
                    ldsm_x4_t(af[mb], smA + SWZ256(krow * 256 + mcol * 2));
                }
            } else {
                #pragma unroll
                for (int mb = 0; mb < 4; ++mb) {
                    int row = wm + mb * 16 + (lane & 15);
                    ldsm_x4(af[mb], smA + SWZ(row * 128 + kb + ((lane >> 4) << 4)));
                }
            }
            #pragma unroll
            for (int npair = 0; npair < 4; ++npair) {
                int row = wn + npair * 16 + (lane & 7) + ((lane >> 4) << 3);
                uint32_t r4[4];
                ldsm_x4(r4, smB + SWZ(row * 128 + kb + (((lane >> 3) & 1) << 4)));
                bf[npair*2  ][0] = r4[0]; bf[npair*2  ][1] = r4[1];
                bf[npair*2+1][0] = r4[2]; bf[npair*2+1][1] = r4[3];
            }
            #pragma unroll
            for (int mb = 0; mb < 4; ++mb)
                #pragma unroll
                for (int nb = 0; nb < 8; ++nb)
                    mma16816(acc[mb][nb], af[mb], bf[nb]);
        }
        __syncthreads();
    }

    // ---------------- epilogue ----------------
    const int erow = lane >> 2;
    const int ecol = (lane & 3) * 2;
    #pragma unroll
    for (int mb = 0; mb < 4; ++mb) {
        #pragma unroll
        for (int nb = 0; nb < 8; ++nb) {
            float* cc = acc[mb][nb];
            const int gm = m0 + wm + mb * 16 + erow;
            const int gc = n0 + wn + nb * 8 + ecol;
            if (EPI == 0) {
                float* ob = (float*)outp + (long)z * outBatch;
                *(float2*)(ob + (long)gm * ldOut + gc)       = make_float2(cc[0], cc[1]);
                *(float2*)(ob + (long)(gm + 8) * ldOut + gc) = make_float2(cc[2], cc[3]);
            } else if (EPI == 4) {
                __half* ob = (__half*)outp + (long)z * outBatch;
                #pragma unroll
                for (int h = 0; h < 2; ++h) {
                    int gmm = gm + h * 8;
                    float bv = biasp[gmm];
                    __half2 hv = __floats2half2_rn(cc[h * 2] + bv, cc[h * 2 + 1] + bv);
                    *(__half2*)(ob + (long)gmm * ldOut + gc) = hv;
                }
            } else {
                __half* ob = (__half*)outp + (long)z * outBatch;
                #pragma unroll
                for (int h = 0; h < 2; ++h) {
                    int gmm = gm + h * 8;
                    float v0 = cc[h * 2], v1 = cc[h * 2 + 1];
                    if (EPI == 2) {
                        v0 = (gc     < outN) ? fmaxf(v0 + biasp[gc],     0.0f) : 0.0f;
                        v1 = (gc + 1 < outN) ? fmaxf(v1 + biasp[gc + 1], 0.0f) : 0.0f;
                    }
                    __half2 hv = __floats2half2_rn(v0, v1);
                    *(__half2*)(ob + (long)gmm * ldOut + gc) = hv;
                }
            }
        }
    }
}

// ---------------------------------------------------------------------------
// split-K reduce: out[i] = sum_z p[z][i]   (fp32, float4 vectorized)
// ---------------------------------------------------------------------------
__global__ __launch_bounds__(256) void reduce_split(const float4* __restrict__ p,
                                                    float4* __restrict__ out, int total4)
{
    const long stride4 = (long)M_TOK * D_IN / 4;
    for (int i = blockIdx.x * 256 + threadIdx.x; i < total4; i += gridDim.x * 256) {
        float4 a = p[i], b = p[i + stride4], c = p[i + 2 * stride4], d = p[i + 3 * stride4];
        out[i] = make_float4(a.x + b.x + c.x + d.x, a.y + b.y + c.y + d.y,
                             a.z + b.z + c.z + d.z, a.w + b.w + c.w + d.w);
    }
}

// ---------------------------------------------------------------------------
// elementwise convert fp32 -> fp16
// ---------------------------------------------------------------------------
__global__ __launch_bounds__(256) void convert_f16(const float* __restrict__ in,
                                                   __half* __restrict__ out, long total)
{
    for (long idx = blockIdx.x * 256L + threadIdx.x; idx < total; idx += (long)gridDim.x * 256)
        out[idx] = __float2half(in[idx]);
}

// ---------------------------------------------------------------------------
// scalar transpose+convert (ragged Cc): fp32 in[R,Cc] -> fp16 out[Cc, segK]
// ---------------------------------------------------------------------------
__global__ __launch_bounds__(256) void transpose_f32(const float* __restrict__ in,
                                                     __half* __restrict__ out,
                                                     int R, int Cc, int segK,
                                                     long inBatch, long outBatch)
{
    __shared__ float t[32][33];
    const int z = blockIdx.z;
    in  += (long)z * inBatch;
    out += (long)z * outBatch;
    const int c0 = blockIdx.x * 32, k0 = blockIdx.y * 32;
    const int tx = threadIdx.x, ty = threadIdx.y;   // 32 x 8

    #pragma unroll
    for (int i = 0; i < 4; ++i) {
        int k = k0 + ty + i * 8, c = c0 + tx;
        float v = 0.0f;
        if (k < R && c < Cc) v = in[(long)k * Cc + c];
        t[ty + i * 8][tx] = v;
    }
    __syncthreads();
    #pragma unroll
    for (int i = 0; i < 4; ++i) {
        int c = c0 + ty + i * 8, k = k0 + tx;
        if (c < Cc && k < segK)
            out[(long)c * segK + k] = __float2half(t[tx][ty + i * 8]);
    }
}

// ---------------------------------------------------------------------------
// vectorized transpose+convert: requires Cc%64==0, segK%64==0.
// 64x64 tile, float4 global loads, 8B packed-half stores.
// out[c][k] = in[k][c] for k<R, 0 for R<=k<segK.
// ---------------------------------------------------------------------------
__global__ __launch_bounds__(256) void transpose_f32_v(const float* __restrict__ in,
                                                       __half* __restrict__ out,
                                                       int R, int Cc, int segK,
                                                       long inBatch, long outBatch)
{
    __shared__ float t[64][65];
    const int z = blockIdx.z;
    in  += (long)z * inBatch;
    out += (long)z * outBatch;
    const int c0 = blockIdx.x * 64, k0 = blockIdx.y * 64;
    const int tx = threadIdx.x & 15;        // c-group (4 floats)
    const int ty = threadIdx.x >> 4;        // 0..15

    #pragma unroll
    for (int i = 0; i < 4; ++i) {
        int k = k0 + ty + i * 16;
        float4 v = make_float4(0.f, 0.f, 0.f, 0.f);
        if (k < R) v = *(const float4*)(in + (long)k * Cc + c0 + tx * 4);
        t[ty + i * 16][tx * 4 + 0] = v.x;
        t[ty + i * 16][tx * 4 + 1] = v.y;
        t[ty + i * 16][tx * 4 + 2] = v.z;
        t[ty + i * 16][tx * 4 + 3] = v.w;
    }
    __syncthreads();
    #pragma unroll
    for (int i = 0; i < 4; ++i) {
        int c  = c0 + ty + i * 16;
        int kk = tx * 4;                     // k within tile
        __half2 h0 = __floats2half2_rn(t[kk + 0][ty + i * 16], t[kk + 1][ty + i * 16]);
        __half2 h1 = __floats2half2_rn(t[kk + 2][ty + i * 16], t[kk + 3][ty + i * 16]);
        uint2 pk;
        pk.x = *(uint32_t*)&h0;
        pk.y = *(uint32_t*)&h1;
        *(uint2*)(out + (long)c * segK + k0 + kk) = pk;
    }
}

// ---------------------------------------------------------------------------
// softmax: per token m, from fp16 logits. Ch (may alias logits) [m,NP], Dh [m,NP]
// ---------------------------------------------------------------------------
__global__ __launch_bounds__(256) void softmax_kernel(const __half* __restrict__ logits,
                                                      __half* __restrict__ Ch,
                                                      __half* __restrict__ Dh)
{
    extern __shared__ float row[];               // 16384 floats
    __shared__ float red[256];
    const int m = blockIdx.x, tid = threadIdx.x;
    const __half* lrow = logits + (size_t)m * NP;

    float mx = -INFINITY;
    for (int i = tid; i < NP; i += 256) { float v = __half2float(lrow[i]); row[i] = v; mx = fmaxf(mx, v); }
    red[tid] = mx; __syncthreads();
    for (int s = 128; s > 0; s >>= 1) { if (tid < s) red[tid] = fmaxf(red[tid], red[tid + s]); __syncthreads(); }
    mx = red[0]; __syncthreads();

    float sum = 0.0f;
    for (int i = tid; i < NP; i += 256) sum += expf(row[i] - mx);
    red[tid] = sum; __syncthreads();
    for (int s = 128; s > 0; s >>= 1) { if (tid < s) red[tid] += red[tid + s]; __syncthreads(); }
    const float inv = 1.0f / red[0];

    __half* crow = Ch + (size_t)m * NP;
    for (int i = tid; i < NP; i += 256)
        crow[i] = __float2half(expf(row[i] - mx) * inv);

    __half* drow = Dh + (size_t)m * NP;
    for (int p = tid; p < P_SLOT; p += 256) {
        float l[N_EXP], mn = -INFINITY;
        #pragma unroll
        for (int n = 0; n < N_EXP; n++) { l[n] = row[n * P_SLOT + p]; mn = fmaxf(mn, l[n]); }
        float s2 = 0.0f;
        #pragma unroll
        for (int n = 0; n < N_EXP; n++) { l[n] = expf(l[n] - mn); s2 += l[n]; }
        const float inv2 = 1.0f / s2;
        #pragma unroll
        for (int n = 0; n < N_EXP; n++) drow[n * P_SLOT + p] = __float2half(l[n] * inv2);
    }
}

// ---------------------------------------------------------------------------
extern "C" void kernel_launch(void* const* d_in, const int* in_sizes, int n_in,
                              void* d_out, int out_size)
{
    const float* x   = (const float*)d_in[0];
    const float* phi = (const float*)d_in[1];
    const float* W1  = (const float*)d_in[2];
    const float* b1  = (const float*)d_in[3];
    const float* W2  = (const float*)d_in[4];
    const float* b2  = (const float*)d_in[5];
    float* out = (float*)d_out;

    __half *Ch, *Dh, *xf, *xT, *phiT, *W1T, *W2T, *Xs, *H, *YsT;
    float *Yp;
    cudaGetSymbolAddress((void**)&Ch,   g_Ch);
    cudaGetSymbolAddress((void**)&Dh,   g_Dh);
    cudaGetSymbolAddress((void**)&xf,   g_xf);
    cudaGetSymbolAddress((void**)&xT,   g_xT);
    cudaGetSymbolAddress((void**)&phiT, g_phiT);
    cudaGetSymbolAddress((void**)&W1T,  g_W1T);
    cudaGetSymbolAddress((void**)&W2T,  g_W2T);
    cudaGetSymbolAddress((void**)&Xs,   g_Xs);
    cudaGetSymbolAddress((void**)&H,    g_H);
    cudaGetSymbolAddress((void**)&YsT,  g_YsT);
    cudaGetSymbolAddress((void**)&Yp,   g_Yp);

    cudaFuncSetAttribute(gemm_f16<0,false,false>, cudaFuncAttributeMaxDynamicSharedMemorySize, SMEM_GEMM);
    cudaFuncSetAttribute(gemm_f16<1,false,false>, cudaFuncAttributeMaxDynamicSharedMemorySize, SMEM_GEMM);
    cudaFuncSetAttribute(gemm_f16<1,false,true>,  cudaFuncAttributeMaxDynamicSharedMemorySize, SMEM_GEMM);
    cudaFuncSetAttribute(gemm_f16<2,true,false>,  cudaFuncAttributeMaxDynamicSharedMemorySize, SMEM_GEMM);
    cudaFuncSetAttribute(gemm_f16<4,false,false>, cudaFuncAttributeMaxDynamicSharedMemorySize, SMEM_GEMM);
    cudaFuncSetAttribute(softmax_kernel,          cudaFuncAttributeMaxDynamicSharedMemorySize, NP * 4);

    dim3 t128(128), t256(256), t32x8(32, 8);

    // operand prep
    convert_f16<<<2048, t256>>>(x, xf, (long)M_TOK * D_IN);
    transpose_f32_v<<<dim3(NP/64, D_IN/64, 1),    t256>>>(phi, phiT, D_IN, NP, D_IN, 0, 0);
    transpose_f32_v<<<dim3(D_IN/64, M_TOK/64, 1), t256>>>(x, xT, M_TOK, D_IN, M_TOK, 0, 0);
    transpose_f32<<<dim3(43, D_IN/32, N_EXP),     t32x8>>>(W1, W1T, D_IN, H_HID, D_IN,
                                                  (long)D_IN*H_HID, (long)H_HID*D_IN);
    transpose_f32_v<<<dim3(P_SLOT/64, H_PAD/64, N_EXP), t256>>>(W2, W2T, H_HID, P_SLOT, H_PAD,
                                                  (long)H_HID*P_SLOT, (long)P_SLOT*H_PAD);

    // 1) logits(fp16, into Ch) = x @ phi   (M=4096, N=16384, K=1024)
    gemm_f16<1,false,false><<<dim3(M_TOK/128, NP/128), t128, SMEM_GEMM>>>(
        xf, phiT, nullptr, Ch, D_IN, NP, D_IN, D_IN, 0,0,0,0, NP, 0);

    // 2) softmaxes: Ch (in place), Dh
    softmax_kernel<<<M_TOK, t256, NP*4>>>(Ch, Ch, Dh);

    // 3) Xs = D^T @ x  via A-trans directly on Dh (M=16384 slots, N=1024, K=4096 tokens)
    gemm_f16<1,false,true><<<dim3(NP/128, D_IN/128), t128, SMEM_GEMM>>>(
        Dh, xT, nullptr, Xs, M_TOK, D_IN, NP, M_TOK, 0,0,0,0, D_IN, 0);

    // 4) H = relu(Xs @ W1 + b1)  per expert (M=1024, N=1365->1408, K=1024)
    gemm_f16<2,true,false><<<dim3(P_SLOT/128, 11, N_EXP), t128, SMEM_GEMM>>>(
        Xs, W1T, b1, H, D_IN, H_HID, D_IN, D_IN,
        (long)P_SLOT*D_IN, (long)H_HID*D_IN, H_HID, (long)P_SLOT*H_PAD, H_PAD, H_HID);

    // 5) YsT[o, n*1024+p] = W2T[n] @ H[n]^T + b2[o]  (M=1024 o, N=1024 p, K=1408)
    gemm_f16<4,false,false><<<dim3(P_SLOT/128, P_SLOT/128, N_EXP), t128, SMEM_GEMM>>>(
        W2T, H, b2, YsT, H_PAD, P_SLOT, H_PAD, H_PAD,
        (long)P_SLOT*H_PAD, (long)P_SLOT*H_PAD, P_SLOT, P_SLOT, NP, 0);

    // 6) Y partials = C @ Ys^T split-K=4  (M=4096, N=1024, K=4x4096) -> fp32 partials
    gemm_f16<0,false,false><<<dim3(M_TOK/128, D_IN/128, SPLITK), t128, SMEM_GEMM>>>(
        Ch, YsT, nullptr, Yp, NP/SPLITK, D_IN, NP, NP,
        NP/SPLITK, NP/SPLITK, 0, (long)M_TOK*D_IN, D_IN, 0);

    // 7) reduce partials -> out
    reduce_split<<<4096, t256>>>((const float4*)Yp, (float4*)out, M_TOK * D_IN / 4);

    (void)in_sizes; (void)n_in; (void)out_size;
}

// round 14
// speedup vs baseline: 1.0100x; 1.0011x over previous
#include <cuda_runtime.h>
#include <cuda_fp16.h>
#include <math.h>
#include <stdint.h>

// ---------------- problem dims ----------------
#define M_TOK 4096
#define D_IN  1024
#define N_EXP 16
#define P_SLOT 1024
#define H_HID 1365
#define H_PAD 1408
#define NP    16384
#define SPLITK 4

// ---------------- scratch ----------------
__device__ __half g_Ch  [(size_t)M_TOK*NP];           // logits then combine weights (in place)
__device__ __half g_Dh  [(size_t)M_TOK*NP];           // dispatch weights [m, np] (MN-major A)
__device__ __half g_xf  [(size_t)M_TOK*D_IN];         // x fp16 [m, d]
__device__ __half g_phif[(size_t)D_IN*NP];            // phi fp16 [d, np]  (MN-major B)
__device__ __half g_W1f [(size_t)N_EXP*D_IN*H_PAD];   // [n][d, h_pad] cols zero-padded (MN-major B)
__device__ __half g_W2f [(size_t)N_EXP*H_PAD*P_SLOT]; // [n][h_pad, o] rows zero-padded (MN-major A)
__device__ __half g_Xs  [(size_t)NP*D_IN];            // slot inputs [np, d]
__device__ __half g_H   [(size_t)N_EXP*P_SLOT*H_PAD]; // hidden [n][p, h_pad] (pad cols zero)
__device__ __half g_YsT [(size_t)P_SLOT*NP];          // slot outputs transposed [o, np]
__device__ float  g_Yp  [(size_t)SPLITK*M_TOK*D_IN];  // combine split-K partials

// ---------------- helpers ----------------
__device__ __forceinline__ uint32_t smem_u32(const void* p) {
    return (uint32_t)__cvta_generic_to_shared(p);
}
#define SWZ(x)    ((x) ^ (((x) >> 3) & 0x70))   // 128B-row swizzle
#define SWZ256(x) ((x) ^ (((x) >> 4) & 0xF0))   // 256B-row swizzle (trans tiles)

__device__ __forceinline__ void ldsm_x4(uint32_t* r, uint32_t addr) {
    asm volatile("ldmatrix.sync.aligned.m8n8.x4.shared.b16 {%0,%1,%2,%3}, [%4];"
                 : "=r"(r[0]), "=r"(r[1]), "=r"(r[2]), "=r"(r[3]) : "r"(addr));
}
__device__ __forceinline__ void ldsm_x4_t(uint32_t* r, uint32_t addr) {
    asm volatile("ldmatrix.sync.aligned.m8n8.x4.trans.shared.b16 {%0,%1,%2,%3}, [%4];"
                 : "=r"(r[0]), "=r"(r[1]), "=r"(r[2]), "=r"(r[3]) : "r"(addr));
}
__device__ __forceinline__ void mma16816(float* c, const uint32_t* a, const uint32_t* b) {
    asm volatile("mma.sync.aligned.m16n8k16.row.col.f32.f16.f16.f32 "
        "{%0,%1,%2,%3}, {%4,%5,%6,%7}, {%8,%9}, {%0,%1,%2,%3};"
        : "+f"(c[0]), "+f"(c[1]), "+f"(c[2]), "+f"(c[3])
        : "r"(a[0]), "r"(a[1]), "r"(a[2]), "r"(a[3]), "r"(b[0]), "r"(b[1]));
}
__device__ __forceinline__ void cp16(uint32_t dst, const void* src, int srcsize) {
    asm volatile("cp.async.cg.shared.global [%0], [%1], 16, %2;"
                 :: "r"(dst), "l"(src), "r"(srcsize) : "memory");
}
#define CP_COMMIT() asm volatile("cp.async.commit_group;" ::: "memory")
#define CP_WAIT(n)  asm volatile("cp.async.wait_group %0;" :: "n"(n) : "memory")

#define STG_BYTES  32768
#define SMEM_GEMM  (2 * STG_BYTES)

// ---------------------------------------------------------------------------
// fp16 HMMA GEMM (R11 engine): D[128,128] = A * B^T (conceptual A[M,K], B[N,K])
//  ATR: A stored [K,M] MN-major, loaded via ldmatrix.trans  (validated R11)
//  BTR: B stored [K,N] MN-major, loaded via ldmatrix.trans  (map by same analogy)
// CTA 128x128, 4 warps each 64x64, 2-stage cp.async, launch_bounds(128,2).
// EPI: 0 = fp32 row-major at z*outBatch (split-K partials)
//      1 = fp16 row-major (ldOut)
//      2 = fp16 row-major + bias[col] + relu + zero cols >= outN
//      4 = fp16 row-major + bias[row], batch column offset z*outBatch
// ---------------------------------------------------------------------------
template<int EPI, bool ATR, bool BTR>
__global__ __launch_bounds__(128, 2)
void gemm_f16(const __half* __restrict__ A, const __half* __restrict__ B,
              const float* __restrict__ bias, void* __restrict__ outp,
              int K, int ldA, int ldB,
              long sA, long sB, long sBias, long outBatch,
              int ldOut, int outN)
{
    extern __shared__ char smraw[];
    const uint32_t smb = smem_u32(smraw);
    const int tid = threadIdx.x, wid = tid >> 5, lane = tid & 31;
    const int z  = blockIdx.z;
    const int m0 = blockIdx.x * 128, n0 = blockIdx.y * 128;
    A += (long)z * sA;
    B += (long)z * sB;
    const float* biasp = bias ? (bias + (long)z * sBias) : bias;

    const int nCh = K >> 6;
    const int lrow = tid >> 3;        // 0..15
    const int lj   = tid & 7;         // 16B lane within 128B row
    const int lrow2 = tid >> 4;       // 0..7   (trans tiles: 256B rows)
    const int lj2   = tid & 15;       // 16B chunk within 256B row

    auto issue = [&](int c) {
        const uint32_t smA = smb + (c & 1) * STG_BYTES;
        const uint32_t smB = smA + 16384;
        const long kb = (long)c * 64 + lj * 8;
        if (ATR) {
            #pragma unroll
            for (int i = 0; i < 8; ++i) {
                int r = lrow2 + i * 8;
                cp16(smA + SWZ256(r * 256 + lj2 * 16),
                     A + (long)(c * 64 + r) * ldA + (m0 + lj2 * 8), 16);
            }
        } else {
            #pragma unroll
            for (int i = 0; i < 8; ++i) {
                int r = lrow + i * 16;
                cp16(smA + SWZ(r * 128 + lj * 16), A + (long)(m0 + r) * ldA + kb, 16);
            }
        }
        if (BTR) {
            #pragma unroll
            for (int i = 0; i < 8; ++i) {
                int r = lrow2 + i * 8;
                cp16(smB + SWZ256(r * 256 + lj2 * 16),
                     B + (long)(c * 64 + r) * ldB + (n0 + lj2 * 8), 16);
            }
        } else {
            #pragma unroll
            for (int i = 0; i < 8; ++i) {
                int r = lrow + i * 16;
                cp16(smB + SWZ(r * 128 + lj * 16), B + (long)(n0 + r) * ldB + kb, 16);
            }
        }
        CP_COMMIT();
    };

    float acc[4][8][4] = {};
    const int wm = (wid >> 1) * 64;
    const int wn = (wid & 1) * 64;

    issue(0);

    for (int c = 0; c < nCh; ++c) {
        if (c + 1 < nCh) { issue(c + 1); CP_WAIT(1); } else { CP_WAIT(0); }
        __syncthreads();

        const uint32_t smA = smb + (c & 1) * STG_BYTES;
        const uint32_t smB = smA + 16384;

        #pragma unroll
        for (int ks = 0; ks < 4; ++ks) {
            const int kb = ks * 32;
            uint32_t af[4][4], bf[8][2];
            if (ATR) {
                // matrices: (m_lo,k_lo),(m_hi,k_lo),(m_lo,k_hi),(m_hi,k_hi)
                const int krow = ks * 16 + (lane & 7) + ((lane >> 4) << 3);
                const int msub = ((lane >> 3) & 1) << 3;
                #pragma unroll
                for (int mb = 0; mb < 4; ++mb) {
                    int mcol = wm + mb * 16 + msub;
                    ldsm_x4_t(af[mb], smA + SWZ256(krow * 256 + mcol * 2));
                }
            } else {
                #pragma unroll
                for (int mb = 0; mb < 4; ++mb) {
                    int row = wm + mb * 16 + (lane & 15);
                    ldsm_x4(af[mb], smA + SWZ(row * 128 + kb + ((lane >> 4) << 4)));
                }
            }
            if (BTR) {
                // matrices: (n_lo,k_lo),(n_lo,k_hi),(n_hi,k_lo),(n_hi,k_hi)
                const int krow = ks * 16 + (lane & 7) + (((lane >> 3) & 1) << 3);
                const int nsub = (lane >> 4) << 3;
                #pragma unroll
                for (int npair = 0; npair < 4; ++npair) {
                    int ncol = wn + npair * 16 + nsub;
                    uint32_t r4[4];
                    ldsm_x4_t(r4, smB + SWZ256(krow * 256 + ncol * 2));
                    bf[npair*2  ][0] = r4[0]; bf[npair*2  ][1] = r4[1];
                    bf[npair*2+1][0] = r4[2]; bf[npair*2+1][1] = r4[3];
                }
            } else {
                #pragma unroll
                for (int npair = 0; npair < 4; ++npair) {
                    int row = wn + npair * 16 + (lane & 7) + ((lane >> 4) << 3);
                    uint32_t r4[4];
                    ldsm_x4(r4, smB + SWZ(row * 128 + kb + (((lane >> 3) & 1) << 4)));
                    bf[npair*2  ][0] = r4[0]; bf[npair*2  ][1] = r4[1];
                    bf[npair*2+1][0] = r4[2]; bf[npair*2+1][1] = r4[3];
                }
            }
            #pragma unroll
            for (int mb = 0; mb < 4; ++mb)
                #pragma unroll
                for (int nb = 0; nb < 8; ++nb)
                    mma16816(acc[mb][nb], af[mb], bf[nb]);
        }
        __syncthreads();
    }

    // ---------------- epilogue ----------------
    const int erow = lane >> 2;
    const int ecol = (lane & 3) * 2;
    #pragma unroll
    for (int mb = 0; mb < 4; ++mb) {
        #pragma unroll
        for (int nb = 0; nb < 8; ++nb) {
            float* cc = acc[mb][nb];
            const int gm = m0 + wm + mb * 16 + erow;
            const int gc = n0 + wn + nb * 8 + ecol;
            if (EPI == 0) {
                float* ob = (float*)outp + (long)z * outBatch;
                *(float2*)(ob + (long)gm * ldOut + gc)       = make_float2(cc[0], cc[1]);
                *(float2*)(ob + (long)(gm + 8) * ldOut + gc) = make_float2(cc[2], cc[3]);
            } else if (EPI == 4) {
                __half* ob = (__half*)outp + (long)z * outBatch;
                #pragma unroll
                for (int h = 0; h < 2; ++h) {
                    int gmm = gm + h * 8;
                    float bv = biasp[gmm];
                    __half2 hv = __floats2half2_rn(cc[h * 2] + bv, cc[h * 2 + 1] + bv);
                    *(__half2*)(ob + (long)gmm * ldOut + gc) = hv;
                }
            } else {
                __half* ob = (__half*)outp + (long)z * outBatch;
                #pragma unroll
                for (int h = 0; h < 2; ++h) {
                    int gmm = gm + h * 8;
                    float v0 = cc[h * 2], v1 = cc[h * 2 + 1];
                    if (EPI == 2) {
                        v0 = (gc     < outN) ? fmaxf(v0 + biasp[gc],     0.0f) : 0.0f;
                        v1 = (gc + 1 < outN) ? fmaxf(v1 + biasp[gc + 1], 0.0f) : 0.0f;
                    }
                    __half2 hv = __floats2half2_rn(v0, v1);
                    *(__half2*)(ob + (long)gmm * ldOut + gc) = hv;
                }
            }
        }
    }
}

// ---------------------------------------------------------------------------
// split-K reduce: out[i] = sum_z p[z][i]
// ---------------------------------------------------------------------------
__global__ __launch_bounds__(256) void reduce_split(const float4* __restrict__ p,
                                                    float4* __restrict__ out, int total4)
{
    const long stride4 = (long)M_TOK * D_IN / 4;
    for (int i = blockIdx.x * 256 + threadIdx.x; i < total4; i += gridDim.x * 256) {
        float4 a = p[i], b = p[i + stride4], c = p[i + 2 * stride4], d = p[i + 3 * stride4];
        out[i] = make_float4(a.x + b.x + c.x + d.x, a.y + b.y + c.y + d.y,
                             a.z + b.z + c.z + d.z, a.w + b.w + c.w + d.w);
    }
}

// ---------------------------------------------------------------------------
// vectorized convert fp32 -> fp16 (total % 4 == 0, pointers 16B-aligned)
// ---------------------------------------------------------------------------
__global__ __launch_bounds__(256) void convert_f16_v(const float4* __restrict__ in,
                                                     uint2* __restrict__ out, long total4)
{
    for (long i = blockIdx.x * 256L + threadIdx.x; i < total4; i += (long)gridDim.x * 256) {
        float4 v = in[i];
        __half2 h0 = __floats2half2_rn(v.x, v.y);
        __half2 h1 = __floats2half2_rn(v.z, v.w);
        uint2 pk; pk.x = *(uint32_t*)&h0; pk.y = *(uint32_t*)&h1;
        out[i] = pk;
    }
}

// ---------------------------------------------------------------------------
// convert with zero pad: fp32 in[R,C] -> fp16 out[Rp,Cp], out[r][c]=in[r][c] or 0
// (Cp even; half2 stores, coalesced)
// ---------------------------------------------------------------------------
__global__ __launch_bounds__(256) void convert_pad(const float* __restrict__ in,
                                                   __half* __restrict__ out,
                                                   int R, int C, int Rp, int Cp,
                                                   long inBatch, long outBatch)
{
    const int z = blockIdx.z;
    in  += (long)z * inBatch;
    out += (long)z * outBatch;
    long total2 = (long)Rp * Cp / 2;
    for (long i = blockIdx.x * 256L + threadIdx.x; i < total2; i += (long)gridDim.x * 256) {
        int c = (int)((i * 2) % Cp);
        int r = (int)((i * 2) / Cp);
        float v0 = 0.f, v1 = 0.f;
        if (r < R) {
            if (c     < C) v0 = in[(long)r * C + c];
            if (c + 1 < C) v1 = in[(long)r * C + c + 1];
        }
        *(__half2*)(out + (long)r * Cp + c) = __floats2half2_rn(v0, v1);
    }
}

// ---------------------------------------------------------------------------
// softmax: per token m, from fp16 logits. Ch (aliases logits) [m,NP], Dh [m,NP]
// ---------------------------------------------------------------------------
__global__ __launch_bounds__(256) void softmax_kernel(const __half* __restrict__ logits,
                                                      __half* __restrict__ Ch,
                                                      __half* __restrict__ Dh)
{
    extern __shared__ float row[];
    __shared__ float red[256];
    const int m = blockIdx.x, tid = threadIdx.x;
    const __half* lrow = logits + (size_t)m * NP;

    float mx = -INFINITY;
    for (int i = tid; i < NP; i += 256) { float v = __half2float(lrow[i]); row[i] = v; mx = fmaxf(mx, v); }
    red[tid] = mx; __syncthreads();
    for (int s = 128; s > 0; s >>= 1) { if (tid < s) red[tid] = fmaxf(red[tid], red[tid + s]); __syncthreads(); }
    mx = red[0]; __syncthreads();

    float sum = 0.0f;
    for (int i = tid; i < NP; i += 256) sum += expf(row[i] - mx);
    red[tid] = sum; __syncthreads();
    for (int s = 128; s > 0; s >>= 1) { if (tid < s) red[tid] += red[tid + s]; __syncthreads(); }
    const float inv = 1.0f / red[0];

    __half* crow = Ch + (size_t)m * NP;
    for (int i = tid; i < NP; i += 256)
        crow[i] = __float2half(expf(row[i] - mx) * inv);

    __half* drow = Dh + (size_t)m * NP;
    for (int p = tid; p < P_SLOT; p += 256) {
        float l[N_EXP], mn = -INFINITY;
        #pragma unroll
        for (int n = 0; n < N_EXP; n++) { l[n] = row[n * P_SLOT + p]; mn = fmaxf(mn, l[n]); }
        float s2 = 0.0f;
        #pragma unroll
        for (int n = 0; n < N_EXP; n++) { l[n] = expf(l[n] - mn); s2 += l[n]; }
        const float inv2 = 1.0f / s2;
        #pragma unroll
        for (int n = 0; n < N_EXP; n++) drow[n * P_SLOT + p] = __float2half(l[n] * inv2);
    }
}

// ---------------------------------------------------------------------------
extern "C" void kernel_launch(void* const* d_in, const int* in_sizes, int n_in,
                              void* d_out, int out_size)
{
    const float* x   = (const float*)d_in[0];
    const float* phi = (const float*)d_in[1];
    const float* W1  = (const float*)d_in[2];
    const float* b1  = (const float*)d_in[3];
    const float* W2  = (const float*)d_in[4];
    const float* b2  = (const float*)d_in[5];
    float* out = (float*)d_out;

    __half *Ch, *Dh, *xf, *phif, *W1f, *W2f, *Xs, *H, *YsT;
    float *Yp;
    cudaGetSymbolAddress((void**)&Ch,   g_Ch);
    cudaGetSymbolAddress((void**)&Dh,   g_Dh);
    cudaGetSymbolAddress((void**)&xf,   g_xf);
    cudaGetSymbolAddress((void**)&phif, g_phif);
    cudaGetSymbolAddress((void**)&W1f,  g_W1f);
    cudaGetSymbolAddress((void**)&W2f,  g_W2f);
    cudaGetSymbolAddress((void**)&Xs,   g_Xs);
    cudaGetSymbolAddress((void**)&H,    g_H);
    cudaGetSymbolAddress((void**)&YsT,  g_YsT);
    cudaGetSymbolAddress((void**)&Yp,   g_Yp);

    cudaFuncSetAttribute(gemm_f16<1,false,true>,  cudaFuncAttributeMaxDynamicSharedMemorySize, SMEM_GEMM);
    cudaFuncSetAttribute(gemm_f16<1,true,true>,   cudaFuncAttributeMaxDynamicSharedMemorySize, SMEM_GEMM);
    cudaFuncSetAttribute(gemm_f16<2,false,true>,  cudaFuncAttributeMaxDynamicSharedMemorySize, SMEM_GEMM);
    cudaFuncSetAttribute(gemm_f16<4,true,false>,  cudaFuncAttributeMaxDynamicSharedMemorySize, SMEM_GEMM);
    cudaFuncSetAttribute(gemm_f16<0,false,false>, cudaFuncAttributeMaxDynamicSharedMemorySize, SMEM_GEMM);
    cudaFuncSetAttribute(softmax_kernel,          cudaFuncAttributeMaxDynamicSharedMemorySize, NP * 4);

    dim3 t128(128), t256(256);

    // operand prep (pure streaming converts; NO transposes)
    convert_f16_v<<<1024, t256>>>((const float4*)x,   (uint2*)xf,   (long)M_TOK * D_IN / 4);
    convert_f16_v<<<4096, t256>>>((const float4*)phi, (uint2*)phif, (long)D_IN * NP / 4);
    convert_pad<<<dim3(1024, 1, N_EXP), t256>>>(W1, W1f, D_IN, H_HID, D_IN, H_PAD,
                                                (long)D_IN * H_HID, (long)D_IN * H_PAD);
    convert_pad<<<dim3(1024, 1, N_EXP), t256>>>(W2, W2f, H_HID, P_SLOT, H_PAD, P_SLOT,
                                                (long)H_HID * P_SLOT, (long)H_PAD * P_SLOT);

    // 1) logits(fp16, into Ch) = x @ phi   (M=4096, N=16384, K=1024); B=phif MN-major
    gemm_f16<1,false,true><<<dim3(M_TOK/128, NP/128), t128, SMEM_GEMM>>>(
        xf, phif, nullptr, Ch, D_IN, D_IN, NP, 0,0,0,0, NP, 0);

    // 2) softmaxes: Ch (in place), Dh
    softmax_kernel<<<M_TOK, t256, NP*4>>>(Ch, Ch, Dh);

    // 3) Xs = D^T @ x: A=Dh MN-major (ATR), B=xf MN-major (BTR)  (M=16384, N=1024, K=4096)
    gemm_f16<1,true,true><<<dim3(NP/128, D_IN/128), t128, SMEM_GEMM>>>(
        Dh, xf, nullptr, Xs, M_TOK, NP, D_IN, 0,0,0,0, D_IN, 0);

    // 4) H = relu(Xs @ W1 + b1): B=W1f MN-major (M=1024, N=1408(pad), K=1024)
    gemm_f16<2,false,true><<<dim3(P_SLOT/128, H_PAD/128, N_EXP), t128, SMEM_GEMM>>>(
        Xs, W1f, b1, H, D_IN, D_IN, H_PAD,
        (long)P_SLOT*D_IN, (long)D_IN*H_PAD, H_HID, (long)P_SLOT*H_PAD, H_PAD, H_HID);

    // 5) YsT[o, n*1024+p] = W2^T[o,:] . H[p,:] + b2[o]: A=W2f MN-major (ATR), B=H
    //    (M=1024 o, N=1024 p, K=1408)
    gemm_f16<4,true,false><<<dim3(P_SLOT/128, P_SLOT/128, N_EXP), t128, SMEM_GEMM>>>(
        W2f, H, b2, YsT, H_PAD, P_SLOT, H_PAD,
        (long)H_PAD*P_SLOT, (long)P_SLOT*H_PAD, P_SLOT, P_SLOT, NP, 0);

    // 6) Y partials = C @ Ys^T split-K=4 -> fp32 partials
    gemm_f16<0,false,false><<<dim3(M_TOK/128, D_IN/128, SPLITK), t128, SMEM_GEMM>>>(
        Ch, YsT, nullptr, Yp, NP/SPLITK, NP, NP,
        NP/SPLITK, NP/SPLITK, 0, (long)M_TOK*D_IN, D_IN, 0);

    // 7) reduce partials -> out
    reduce_split<<<4096, t256>>>((const float4*)Yp, (float4*)out, M_TOK * D_IN / 4);

    (void)in_sizes; (void)n_in; (void)out_size;
}

// round 15
// speedup vs baseline: 1.0347x; 1.0244x over previous
#include <cuda_runtime.h>
#include <cuda_fp16.h>
#include <math.h>
#include <stdint.h>

// ---------------- problem dims ----------------
#define M_TOK 4096
#define D_IN  1024
#define N_EXP 16
#define P_SLOT 1024
#define H_HID 1365
#define H_PAD 1408
#define NP    16384
#define SPLITK 4

// ---------------- scratch ----------------
__device__ __half g_Ch  [(size_t)M_TOK*NP];           // logits then combine weights (in place)
__device__ __half g_Dh  [(size_t)M_TOK*NP];           // dispatch weights [m, np] (MN-major A)
__device__ __half g_xf  [(size_t)M_TOK*D_IN];         // x fp16 [m, d]
__device__ __half g_phif[(size_t)D_IN*NP];            // phi fp16 [d, np]  (MN-major B)
__device__ __half g_W1f [(size_t)N_EXP*D_IN*H_PAD];   // [n][d, h_pad] cols zero-padded (MN-major B)
__device__ __half g_W2f [(size_t)N_EXP*H_HID*P_SLOT]; // [n][h, o] plain fp16 (MN-major A, row-guarded)
__device__ __half g_Xs  [(size_t)NP*D_IN];            // slot inputs [np, d]
__device__ __half g_H   [(size_t)N_EXP*P_SLOT*H_PAD]; // hidden [n][p, h_pad] (pad cols zero)
__device__ __half g_YsT [(size_t)P_SLOT*NP];          // slot outputs transposed [o, np]
__device__ float  g_Yp  [(size_t)SPLITK*M_TOK*D_IN];  // combine split-K partials

// ---------------- helpers ----------------
__device__ __forceinline__ uint32_t smem_u32(const void* p) {
    return (uint32_t)__cvta_generic_to_shared(p);
}
#define SWZ(x)    ((x) ^ (((x) >> 3) & 0x70))   // 128B-row swizzle
#define SWZ256(x) ((x) ^ (((x) >> 4) & 0xF0))   // 256B-row swizzle (trans tiles)

__device__ __forceinline__ void ldsm_x4(uint32_t* r, uint32_t addr) {
    asm volatile("ldmatrix.sync.aligned.m8n8.x4.shared.b16 {%0,%1,%2,%3}, [%4];"
                 : "=r"(r[0]), "=r"(r[1]), "=r"(r[2]), "=r"(r[3]) : "r"(addr));
}
__device__ __forceinline__ void ldsm_x4_t(uint32_t* r, uint32_t addr) {
    asm volatile("ldmatrix.sync.aligned.m8n8.x4.trans.shared.b16 {%0,%1,%2,%3}, [%4];"
                 : "=r"(r[0]), "=r"(r[1]), "=r"(r[2]), "=r"(r[3]) : "r"(addr));
}
__device__ __forceinline__ void mma16816(float* c, const uint32_t* a, const uint32_t* b) {
    asm volatile("mma.sync.aligned.m16n8k16.row.col.f32.f16.f16.f32 "
        "{%0,%1,%2,%3}, {%4,%5,%6,%7}, {%8,%9}, {%0,%1,%2,%3};"
        : "+f"(c[0]), "+f"(c[1]), "+f"(c[2]), "+f"(c[3])
        : "r"(a[0]), "r"(a[1]), "r"(a[2]), "r"(a[3]), "r"(b[0]), "r"(b[1]));
}
__device__ __forceinline__ void cp16(uint32_t dst, const void* src, int srcsize) {
    asm volatile("cp.async.cg.shared.global [%0], [%1], 16, %2;"
                 :: "r"(dst), "l"(src), "r"(srcsize) : "memory");
}
#define CP_COMMIT() asm volatile("cp.async.commit_group;" ::: "memory")
#define CP_WAIT(n)  asm volatile("cp.async.wait_group %0;" :: "n"(n) : "memory")

#define STG_BYTES  32768
#define SMEM_GEMM  (2 * STG_BYTES)

// ---------------------------------------------------------------------------
// fp16 HMMA GEMM (R11 engine): D[128,128] = A * B^T (conceptual A[M,K], B[N,K])
//  ATR: A stored [K,M] MN-major, loaded via ldmatrix.trans (validated R11)
//  BTR: B stored [K,N] MN-major, loaded via ldmatrix.trans (validated R14)
//  ACHK: ATR rows k >= aRows read as zero (cp.async srcsize=0)
// CTA 128x128, 4 warps each 64x64, 2-stage cp.async, launch_bounds(128,2).
// EPI: 0 = fp32 row-major at z*outBatch (split-K partials)
//      1 = fp16 row-major (ldOut)
//      2 = fp16 row-major + bias[col] + relu + zero cols >= outN
//      4 = fp16 row-major + bias[row], batch column offset z*outBatch
// ---------------------------------------------------------------------------
template<int EPI, bool ATR, bool BTR, bool ACHK>
__global__ __launch_bounds__(128, 2)
void gemm_f16(const __half* __restrict__ A, const __half* __restrict__ B,
              const float* __restrict__ bias, void* __restrict__ outp,
              int K, int ldA, int ldB,
              long sA, long sB, long sBias, long outBatch,
              int ldOut, int outN, int aRows)
{
    extern __shared__ char smraw[];
    const uint32_t smb = smem_u32(smraw);
    const int tid = threadIdx.x, wid = tid >> 5, lane = tid & 31;
    const int z  = blockIdx.z;
    const int m0 = blockIdx.x * 128, n0 = blockIdx.y * 128;
    A += (long)z * sA;
    B += (long)z * sB;
    const float* biasp = bias ? (bias + (long)z * sBias) : bias;

    const int nCh = K >> 6;
    const int lrow = tid >> 3;        // 0..15
    const int lj   = tid & 7;         // 16B lane within 128B row
    const int lrow2 = tid >> 4;       // 0..7   (trans tiles: 256B rows)
    const int lj2   = tid & 15;       // 16B chunk within 256B row

    auto issue = [&](int c) {
        const uint32_t smA = smb + (c & 1) * STG_BYTES;
        const uint32_t smB = smA + 16384;
        const long kb = (long)c * 64 + lj * 8;
        if (ATR) {
            #pragma unroll
            for (int i = 0; i < 8; ++i) {
                int r = lrow2 + i * 8;
                int kk = c * 64 + r;
                int ok = (!ACHK) || (kk < aRows);
                const __half* src = A + (long)(ok ? kk : 0) * ldA + (m0 + lj2 * 8);
                cp16(smA + SWZ256(r * 256 + lj2 * 16), src, ok ? 16 : 0);
            }
        } else {
            #pragma unroll
            for (int i = 0; i < 8; ++i) {
                int r = lrow + i * 16;
                cp16(smA + SWZ(r * 128 + lj * 16), A + (long)(m0 + r) * ldA + kb, 16);
            }
        }
        if (BTR) {
            #pragma unroll
            for (int i = 0; i < 8; ++i) {
                int r = lrow2 + i * 8;
                cp16(smB + SWZ256(r * 256 + lj2 * 16),
                     B + (long)(c * 64 + r) * ldB + (n0 + lj2 * 8), 16);
            }
        } else {
            #pragma unroll
            for (int i = 0; i < 8; ++i) {
                int r = lrow + i * 16;
                cp16(smB + SWZ(r * 128 + lj * 16), B + (long)(n0 + r) * ldB + kb, 16);
            }
        }
        CP_COMMIT();
    };

    float acc[4][8][4] = {};
    const int wm = (wid >> 1) * 64;
    const int wn = (wid & 1) * 64;

    issue(0);

    for (int c = 0; c < nCh; ++c) {
        if (c + 1 < nCh) { issue(c + 1); CP_WAIT(1); } else { CP_WAIT(0); }
        __syncthreads();

        const uint32_t smA = smb + (c & 1) * STG_BYTES;
        const uint32_t smB = smA + 16384;

        #pragma unroll
        for (int ks = 0; ks < 4; ++ks) {
            const int kb = ks * 32;
            uint32_t af[4][4], bf[8][2];
            if (ATR) {
                const int krow = ks * 16 + (lane & 7) + ((lane >> 4) << 3);
                const int msub = ((lane >> 3) & 1) << 3;
                #pragma unroll
                for (int mb = 0; mb < 4; ++mb) {
                    int mcol = wm + mb * 16 + msub;
                    ldsm_x4_t(af[mb], smA + SWZ256(krow * 256 + mcol * 2));
                }
            } else {
                #pragma unroll
                for (int mb = 0; mb < 4; ++mb) {
                    int row = wm + mb * 16 + (lane & 15);
                    ldsm_x4(af[mb], smA + SWZ(row * 128 + kb + ((lane >> 4) << 4)));
                }
            }
            if (BTR) {
                const int krow = ks * 16 + (lane & 7) + (((lane >> 3) & 1) << 3);
                const int nsub = (lane >> 4) << 3;
                #pragma unroll
                for (int npair = 0; npair < 4; ++npair) {
                    int ncol = wn + npair * 16 + nsub;
                    uint32_t r4[4];
                    ldsm_x4_t(r4, smB + SWZ256(krow * 256 + ncol * 2));
                    bf[npair*2  ][0] = r4[0]; bf[npair*2  ][1] = r4[1];
                    bf[npair*2+1][0] = r4[2]; bf[npair*2+1][1] = r4[3];
                }
            } else {
                #pragma unroll
                for (int npair = 0; npair < 4; ++npair) {
                    int row = wn + npair * 16 + (lane & 7) + ((lane >> 4) << 3);
                    uint32_t r4[4];
                    ldsm_x4(r4, smB + SWZ(row * 128 + kb + (((lane >> 3) & 1) << 4)));
                    bf[npair*2  ][0] = r4[0]; bf[npair*2  ][1] = r4[1];
                    bf[npair*2+1][0] = r4[2]; bf[npair*2+1][1] = r4[3];
                }
            }
            #pragma unroll
            for (int mb = 0; mb < 4; ++mb)
                #pragma unroll
                for (int nb = 0; nb < 8; ++nb)
                    mma16816(acc[mb][nb], af[mb], bf[nb]);
        }
        __syncthreads();
    }

    // ---------------- epilogue ----------------
    const int erow = lane >> 2;
    const int ecol = (lane & 3) * 2;
    #pragma unroll
    for (int mb = 0; mb < 4; ++mb) {
        #pragma unroll
        for (int nb = 0; nb < 8; ++nb) {
            float* cc = acc[mb][nb];
            const int gm = m0 + wm + mb * 16 + erow;
            const int gc = n0 + wn + nb * 8 + ecol;
            if (EPI == 0) {
                float* ob = (float*)outp + (long)z * outBatch;
                *(float2*)(ob + (long)gm * ldOut + gc)       = make_float2(cc[0], cc[1]);
                *(float2*)(ob + (long)(gm + 8) * ldOut + gc) = make_float2(cc[2], cc[3]);
            } else if (EPI == 4) {
                __half* ob = (__half*)outp + (long)z * outBatch;
                #pragma unroll
                for (int h = 0; h < 2; ++h) {
                    int gmm = gm + h * 8;
                    float bv = biasp[gmm];
                    __half2 hv = __floats2half2_rn(cc[h * 2] + bv, cc[h * 2 + 1] + bv);
                    *(__half2*)(ob + (long)gmm * ldOut + gc) = hv;
                }
            } else {
                __half* ob = (__half*)outp + (long)z * outBatch;
                #pragma unroll
                for (int h = 0; h < 2; ++h) {
                    int gmm = gm + h * 8;
                    float v0 = cc[h * 2], v1 = cc[h * 2 + 1];
                    if (EPI == 2) {
                        v0 = (gc     < outN) ? fmaxf(v0 + biasp[gc],     0.0f) : 0.0f;
                        v1 = (gc + 1 < outN) ? fmaxf(v1 + biasp[gc + 1], 0.0f) : 0.0f;
                    }
                    __half2 hv = __floats2half2_rn(v0, v1);
                    *(__half2*)(ob + (long)gmm * ldOut + gc) = hv;
                }
            }
        }
    }
}

// ---------------------------------------------------------------------------
// split-K reduce: out[i] = sum_z p[z][i]
// ---------------------------------------------------------------------------
__global__ __launch_bounds__(256) void reduce_split(const float4* __restrict__ p,
                                                    float4* __restrict__ out, int total4)
{
    const long stride4 = (long)M_TOK * D_IN / 4;
    for (int i = blockIdx.x * 256 + threadIdx.x; i < total4; i += gridDim.x * 256) {
        float4 a = p[i], b = p[i + stride4], c = p[i + 2 * stride4], d = p[i + 3 * stride4];
        out[i] = make_float4(a.x + b.x + c.x + d.x, a.y + b.y + c.y + d.y,
                             a.z + b.z + c.z + d.z, a.w + b.w + c.w + d.w);
    }
}

// ---------------------------------------------------------------------------
// vectorized convert fp32 -> fp16 (total % 4 == 0, pointers 16B-aligned)
// ---------------------------------------------------------------------------
__global__ __launch_bounds__(256) void convert_f16_v(const float4* __restrict__ in,
                                                     uint2* __restrict__ out, long total4)
{
    for (long i = blockIdx.x * 256L + threadIdx.x; i < total4; i += (long)gridDim.x * 256) {
        float4 v = in[i];
        __half2 h0 = __floats2half2_rn(v.x, v.y);
        __half2 h1 = __floats2half2_rn(v.z, v.w);
        uint2 pk; pk.x = *(uint32_t*)&h0; pk.y = *(uint32_t*)&h1;
        out[i] = pk;
    }
}

// ---------------------------------------------------------------------------
// row-based pad convert: fp32 in[R,C] -> fp16 out[R,Cp] (cols >= C zero).
// one block per (row, batch); streaming, no div/mod.
// ---------------------------------------------------------------------------
__global__ __launch_bounds__(256) void convert_pad_row(const float* __restrict__ in,
                                                       __half* __restrict__ out,
                                                       int C, int Cp,
                                                       long inBatch, long outBatch)
{
    const int r = blockIdx.x;
    const float* irow = in  + (long)blockIdx.z * inBatch  + (long)r * C;
    __half*      orow = out + (long)blockIdx.z * outBatch + (long)r * Cp;
    for (int c2 = threadIdx.x; c2 < Cp / 2; c2 += 256) {
        int c = c2 * 2;
        float v0 = (c     < C) ? irow[c]     : 0.0f;
        float v1 = (c + 1 < C) ? irow[c + 1] : 0.0f;
        *(__half2*)(orow + c) = __floats2half2_rn(v0, v1);
    }
}

// ---------------------------------------------------------------------------
// softmax: per token m, from fp16 logits. Ch (aliases logits) [m,NP], Dh [m,NP]
// ---------------------------------------------------------------------------
__global__ __launch_bounds__(256) void softmax_kernel(const __half* __restrict__ logits,
                                                      __half* __restrict__ Ch,
                                                      __half* __restrict__ Dh)
{
    extern __shared__ float row[];
    __shared__ float red[256];
    const int m = blockIdx.x, tid = threadIdx.x;
    const __half* lrow = logits + (size_t)m * NP;

    float mx = -INFINITY;
    for (int i = tid; i < NP; i += 256) { float v = __half2float(lrow[i]); row[i] = v; mx = fmaxf(mx, v); }
    red[tid] = mx; __syncthreads();
    for (int s = 128; s > 0; s >>= 1) { if (tid < s) red[tid] = fmaxf(red[tid], red[tid + s]); __syncthreads(); }
    mx = red[0]; __syncthreads();

    float sum = 0.0f;
    for (int i = tid; i < NP; i += 256) sum += expf(row[i] - mx);
    red[tid] = sum; __syncthreads();
    for (int s = 128; s > 0; s >>= 1) { if (tid < s) red[tid] += red[tid + s]; __syncthreads(); }
    const float inv = 1.0f / red[0];

    __half* crow = Ch + (size_t)m * NP;
    for (int i = tid; i < NP; i += 256)
        crow[i] = __float2half(expf(row[i] - mx) * inv);

    __half* drow = Dh + (size_t)m * NP;
    for (int p = tid; p < P_SLOT; p += 256) {
        float l[N_EXP], mn = -INFINITY;
        #pragma unroll
        for (int n = 0; n < N_EXP; n++) { l[n] = row[n * P_SLOT + p]; mn = fmaxf(mn, l[n]); }
        float s2 = 0.0f;
        #pragma unroll
        for (int n = 0; n < N_EXP; n++) { l[n] = expf(l[n] - mn); s2 += l[n]; }
        const float inv2 = 1.0f / s2;
        #pragma unroll
        for (int n = 0; n < N_EXP; n++) drow[n * P_SLOT + p] = __float2half(l[n] * inv2);
    }
}

// ---------------------------------------------------------------------------
extern "C" void kernel_launch(void* const* d_in, const int* in_sizes, int n_in,
                              void* d_out, int out_size)
{
    const float* x   = (const float*)d_in[0];
    const float* phi = (const float*)d_in[1];
    const float* W1  = (const float*)d_in[2];
    const float* b1  = (const float*)d_in[3];
    const float* W2  = (const float*)d_in[4];
    const float* b2  = (const float*)d_in[5];
    float* out = (float*)d_out;

    __half *Ch, *Dh, *xf, *phif, *W1f, *W2f, *Xs, *H, *YsT;
    float *Yp;
    cudaGetSymbolAddress((void**)&Ch,   g_Ch);
    cudaGetSymbolAddress((void**)&Dh,   g_Dh);
    cudaGetSymbolAddress((void**)&xf,   g_xf);
    cudaGetSymbolAddress((void**)&phif, g_phif);
    cudaGetSymbolAddress((void**)&W1f,  g_W1f);
    cudaGetSymbolAddress((void**)&W2f,  g_W2f);
    cudaGetSymbolAddress((void**)&Xs,   g_Xs);
    cudaGetSymbolAddress((void**)&H,    g_H);
    cudaGetSymbolAddress((void**)&YsT,  g_YsT);
    cudaGetSymbolAddress((void**)&Yp,   g_Yp);

    cudaFuncSetAttribute(gemm_f16<1,false,true,false>,  cudaFuncAttributeMaxDynamicSharedMemorySize, SMEM_GEMM);
    cudaFuncSetAttribute(gemm_f16<1,true,true,false>,   cudaFuncAttributeMaxDynamicSharedMemorySize, SMEM_GEMM);
    cudaFuncSetAttribute(gemm_f16<2,false,true,false>,  cudaFuncAttributeMaxDynamicSharedMemorySize, SMEM_GEMM);
    cudaFuncSetAttribute(gemm_f16<4,true,false,true>,   cudaFuncAttributeMaxDynamicSharedMemorySize, SMEM_GEMM);
    cudaFuncSetAttribute(gemm_f16<0,false,false,false>, cudaFuncAttributeMaxDynamicSharedMemorySize, SMEM_GEMM);
    cudaFuncSetAttribute(softmax_kernel,                cudaFuncAttributeMaxDynamicSharedMemorySize, NP * 4);

    dim3 t128(128), t256(256);

    // operand prep (streaming converts only)
    convert_f16_v<<<1024, t256>>>((const float4*)x,   (uint2*)xf,   (long)M_TOK * D_IN / 4);
    convert_f16_v<<<4096, t256>>>((const float4*)phi, (uint2*)phif, (long)D_IN * NP / 4);
    convert_f16_v<<<4096, t256>>>((const float4*)W2,  (uint2*)W2f,  (long)N_EXP * H_HID * P_SLOT / 4);
    convert_pad_row<<<dim3(D_IN, 1, N_EXP), t256>>>(W1, W1f, H_HID, H_PAD,
                                                    (long)D_IN * H_HID, (long)D_IN * H_PAD);

    // 1) logits(fp16, into Ch) = x @ phi   (M=4096, N=16384, K=1024); B=phif MN-major
    gemm_f16<1,false,true,false><<<dim3(M_TOK/128, NP/128), t128, SMEM_GEMM>>>(
        xf, phif, nullptr, Ch, D_IN, D_IN, NP, 0,0,0,0, NP, 0, 0);

    // 2) softmaxes: Ch (in place), Dh
    softmax_kernel<<<M_TOK, t256, NP*4>>>(Ch, Ch, Dh);

    // 3) Xs = D^T @ x: A=Dh MN-major (ATR), B=xf MN-major (BTR)  (M=16384, N=1024, K=4096)
    gemm_f16<1,true,true,false><<<dim3(NP/128, D_IN/128), t128, SMEM_GEMM>>>(
        Dh, xf, nullptr, Xs, M_TOK, NP, D_IN, 0,0,0,0, D_IN, 0, 0);

    // 4) H = relu(Xs @ W1 + b1): B=W1f MN-major (M=1024, N=1408(pad), K=1024)
    gemm_f16<2,false,true,false><<<dim3(P_SLOT/128, H_PAD/128, N_EXP), t128, SMEM_GEMM>>>(
        Xs, W1f, b1, H, D_IN, D_IN, H_PAD,
        (long)P_SLOT*D_IN, (long)D_IN*H_PAD, H_HID, (long)P_SLOT*H_PAD, H_PAD, H_HID, 0);

    // 5) YsT[o, n*1024+p] = W2^T[o,:] . H[p,:] + b2[o]: A=W2f [h,o] (ATR, rows>=1365 zero)
    //    (M=1024 o, N=1024 p, K=1408)
    gemm_f16<4,true,false,true><<<dim3(P_SLOT/128, P_SLOT/128, N_EXP), t128, SMEM_GEMM>>>(
        W2f, H, b2, YsT, H_PAD, P_SLOT, H_PAD,
        (long)H_HID*P_SLOT, (long)P_SLOT*H_PAD, P_SLOT, P_SLOT, NP, 0, H_HID);

    // 6) Y partials = C @ Ys^T split-K=4 -> fp32 partials
    gemm_f16<0,false,false,false><<<dim3(M_TOK/128, D_IN/128, SPLITK), t128, SMEM_GEMM>>>(
        Ch, YsT, nullptr, Yp, NP/SPLITK, NP, NP,
        NP/SPLITK, NP/SPLITK, 0, (long)M_TOK*D_IN, D_IN, 0, 0);

    // 7) reduce partials -> out
    reduce_split<<<4096, t256>>>((const float4*)Yp, (float4*)out, M_TOK * D_IN / 4);

    (void)in_sizes; (void)n_in; (void)out_size;
}

// round 16
// speedup vs baseline: 1.0373x; 1.0025x over previous
#include <cuda_runtime.h>
#include <cuda_fp16.h>
#include <math.h>
#include <stdint.h>

// ---------------- problem dims ----------------
#define M_TOK 4096
#define D_IN  1024
#define N_EXP 16
#define P_SLOT 1024
#define H_HID 1365
#define H_PAD 1408
#define NP    16384
#define SPLITK 4

// ---------------- scratch ----------------
__device__ __half g_Ch  [(size_t)M_TOK*NP];           // logits then combine weights (in place)
__device__ __half g_Dh  [(size_t)M_TOK*NP];           // dispatch weights [m, np] (MN-major A)
__device__ __half g_xf  [(size_t)M_TOK*D_IN];         // x fp16 [m, d]
__device__ __half g_phif[(size_t)D_IN*NP];            // phi fp16 [d, np]  (MN-major B)
__device__ __half g_W1f [(size_t)N_EXP*D_IN*H_PAD];   // [n][d, h_pad] cols zero-padded (MN-major B)
__device__ __half g_W2f [(size_t)N_EXP*H_HID*P_SLOT]; // [n][h, o] plain fp16 (MN-major A, row-guarded)
__device__ __half g_Xs  [(size_t)NP*D_IN];            // slot inputs [np, d]
__device__ __half g_H   [(size_t)N_EXP*P_SLOT*H_PAD]; // hidden [n][p, h_pad] (pad cols zero)
__device__ __half g_YsT [(size_t)P_SLOT*NP];          // slot outputs transposed [o, np]
__device__ float  g_Yp  [(size_t)SPLITK*M_TOK*D_IN];  // combine split-K partials

// ---------------- helpers ----------------
__device__ __forceinline__ uint32_t smem_u32(const void* p) {
    return (uint32_t)__cvta_generic_to_shared(p);
}
#define SWZ(x)    ((x) ^ (((x) >> 3) & 0x70))   // 128B-row swizzle
#define SWZ256(x) ((x) ^ (((x) >> 4) & 0xF0))   // 256B-row swizzle (trans tiles)

__device__ __forceinline__ void ldsm_x4(uint32_t* r, uint32_t addr) {
    asm volatile("ldmatrix.sync.aligned.m8n8.x4.shared.b16 {%0,%1,%2,%3}, [%4];"
                 : "=r"(r[0]), "=r"(r[1]), "=r"(r[2]), "=r"(r[3]) : "r"(addr));
}
__device__ __forceinline__ void ldsm_x4_t(uint32_t* r, uint32_t addr) {
    asm volatile("ldmatrix.sync.aligned.m8n8.x4.trans.shared.b16 {%0,%1,%2,%3}, [%4];"
                 : "=r"(r[0]), "=r"(r[1]), "=r"(r[2]), "=r"(r[3]) : "r"(addr));
}
__device__ __forceinline__ void mma16816(float* c, const uint32_t* a, const uint32_t* b) {
    asm volatile("mma.sync.aligned.m16n8k16.row.col.f32.f16.f16.f32 "
        "{%0,%1,%2,%3}, {%4,%5,%6,%7}, {%8,%9}, {%0,%1,%2,%3};"
        : "+f"(c[0]), "+f"(c[1]), "+f"(c[2]), "+f"(c[3])
        : "r"(a[0]), "r"(a[1]), "r"(a[2]), "r"(a[3]), "r"(b[0]), "r"(b[1]));
}
__device__ __forceinline__ void cp16(uint32_t dst, const void* src, int srcsize) {
    asm volatile("cp.async.cg.shared.global [%0], [%1], 16, %2;"
                 :: "r"(dst), "l"(src), "r"(srcsize) : "memory");
}
#define CP_COMMIT() asm volatile("cp.async.commit_group;" ::: "memory")
#define CP_WAIT(n)  asm volatile("cp.async.wait_group %0;" :: "n"(n) : "memory")

#define STG_BYTES  32768
#define SMEM_GEMM  (2 * STG_BYTES)

// ---------------------------------------------------------------------------
// fp16 HMMA GEMM (R11 engine): D[128,128] = A * B^T (conceptual A[M,K], B[N,K])
//  ATR: A stored [K,M] MN-major, loaded via ldmatrix.trans (validated R11)
//  BTR: B stored [K,N] MN-major, loaded via ldmatrix.trans (validated R14)
//  ACHK: ATR rows k >= aRows read as zero (cp.async srcsize=0)
// CTA 128x128, 4 warps each 64x64, 2-stage cp.async, launch_bounds(128,2).
// EPI: 0 = fp32 row-major at z*outBatch (split-K partials)
//      1 = fp16 row-major (ldOut)
//      2 = fp16 row-major + bias[col] + relu + zero cols >= outN
//      4 = fp16 row-major + bias[row], batch column offset z*outBatch
// ---------------------------------------------------------------------------
template<int EPI, bool ATR, bool BTR, bool ACHK>
__global__ __launch_bounds__(128, 2)
void gemm_f16(const __half* __restrict__ A, const __half* __restrict__ B,
              const float* __restrict__ bias, void* __restrict__ outp,
              int K, int ldA, int ldB,
              long sA, long sB, long sBias, long outBatch,
              int ldOut, int outN, int aRows)
{
    extern __shared__ char smraw[];
    const uint32_t smb = smem_u32(smraw);
    const int tid = threadIdx.x, wid = tid >> 5, lane = tid & 31;
    const int z  = blockIdx.z;
    const int m0 = blockIdx.x * 128, n0 = blockIdx.y * 128;
    A += (long)z * sA;
    B += (long)z * sB;
    const float* biasp = bias ? (bias + (long)z * sBias) : bias;

    const int nCh = K >> 6;
    const int lrow = tid >> 3;        // 0..15
    const int lj   = tid & 7;         // 16B lane within 128B row
    const int lrow2 = tid >> 4;       // 0..7   (trans tiles: 256B rows)
    const int lj2   = tid & 15;       // 16B chunk within 256B row

    auto issue = [&](int c) {
        const uint32_t smA = smb + (c & 1) * STG_BYTES;
        const uint32_t smB = smA + 16384;
        const long kb = (long)c * 64 + lj * 8;
        if (ATR) {
            #pragma unroll
            for (int i = 0; i < 8; ++i) {
                int r = lrow2 + i * 8;
                int kk = c * 64 + r;
                int ok = (!ACHK) || (kk < aRows);
                const __half* src = A + (long)(ok ? kk : 0) * ldA + (m0 + lj2 * 8);
                cp16(smA + SWZ256(r * 256 + lj2 * 16), src, ok ? 16 : 0);
            }
        } else {
            #pragma unroll
            for (int i = 0; i < 8; ++i) {
                int r = lrow + i * 16;
                cp16(smA + SWZ(r * 128 + lj * 16), A + (long)(m0 + r) * ldA + kb, 16);
            }
        }
        if (BTR) {
            #pragma unroll
            for (int i = 0; i < 8; ++i) {
                int r = lrow2 + i * 8;
                cp16(smB + SWZ256(r * 256 + lj2 * 16),
                     B + (long)(c * 64 + r) * ldB + (n0 + lj2 * 8), 16);
            }
        } else {
            #pragma unroll
            for (int i = 0; i < 8; ++i) {
                int r = lrow + i * 16;
                cp16(smB + SWZ(r * 128 + lj * 16), B + (long)(n0 + r) * ldB + kb, 16);
            }
        }
        CP_COMMIT();
    };

    float acc[4][8][4] = {};
    const int wm = (wid >> 1) * 64;
    const int wn = (wid & 1) * 64;

    issue(0);

    for (int c = 0; c < nCh; ++c) {
        if (c + 1 < nCh) { issue(c + 1); CP_WAIT(1); } else { CP_WAIT(0); }
        __syncthreads();

        const uint32_t smA = smb + (c & 1) * STG_BYTES;
        const uint32_t smB = smA + 16384;

        #pragma unroll
        for (int ks = 0; ks < 4; ++ks) {
            const int kb = ks * 32;
            uint32_t af[4][4], bf[8][2];
            if (ATR) {
                const int krow = ks * 16 + (lane & 7) + ((lane >> 4) << 3);
                const int msub = ((lane >> 3) & 1) << 3;
                #pragma unroll
                for (int mb = 0; mb < 4; ++mb) {
                    int mcol = wm + mb * 16 + msub;
                    ldsm_x4_t(af[mb], smA + SWZ256(krow * 256 + mcol * 2));
                }
            } else {
                #pragma unroll
                for (int mb = 0; mb < 4; ++mb) {
                    int row = wm + mb * 16 + (lane & 15);
                    ldsm_x4(af[mb], smA + SWZ(row * 128 + kb + ((lane >> 4) << 4)));
                }
            }
            if (BTR) {
                const int krow = ks * 16 + (lane & 7) + (((lane >> 3) & 1) << 3);
                const int nsub = (lane >> 4) << 3;
                #pragma unroll
                for (int npair = 0; npair < 4; ++npair) {
                    int ncol = wn + npair * 16 + nsub;
                    uint32_t r4[4];
                    ldsm_x4_t(r4, smB + SWZ256(krow * 256 + ncol * 2));
                    bf[npair*2  ][0] = r4[0]; bf[npair*2  ][1] = r4[1];
                    bf[npair*2+1][0] = r4[2]; bf[npair*2+1][1] = r4[3];
                }
            } else {
                #pragma unroll
                for (int npair = 0; npair < 4; ++npair) {
                    int row = wn + npair * 16 + (lane & 7) + ((lane >> 4) << 3);
                    uint32_t r4[4];
                    ldsm_x4(r4, smB + SWZ(row * 128 + kb + (((lane >> 3) & 1) << 4)));
                    bf[npair*2  ][0] = r4[0]; bf[npair*2  ][1] = r4[1];
                    bf[npair*2+1][0] = r4[2]; bf[npair*2+1][1] = r4[3];
                }
            }
            #pragma unroll
            for (int mb = 0; mb < 4; ++mb)
                #pragma unroll
                for (int nb = 0; nb < 8; ++nb)
                    mma16816(acc[mb][nb], af[mb], bf[nb]);
        }
        __syncthreads();
    }

    // ---------------- epilogue ----------------
    const int erow = lane >> 2;
    const int ecol = (lane & 3) * 2;
    #pragma unroll
    for (int mb = 0; mb < 4; ++mb) {
        #pragma unroll
        for (int nb = 0; nb < 8; ++nb) {
            float* cc = acc[mb][nb];
            const int gm = m0 + wm + mb * 16 + erow;
            const int gc = n0 + wn + nb * 8 + ecol;
            if (EPI == 0) {
                float* ob = (float*)outp + (long)z * outBatch;
                *(float2*)(ob + (long)gm * ldOut + gc)       = make_float2(cc[0], cc[1]);
                *(float2*)(ob + (long)(gm + 8) * ldOut + gc) = make_float2(cc[2], cc[3]);
            } else if (EPI == 4) {
                __half* ob = (__half*)outp + (long)z * outBatch;
                #pragma unroll
                for (int h = 0; h < 2; ++h) {
                    int gmm = gm + h * 8;
                    float bv = biasp[gmm];
                    __half2 hv = __floats2half2_rn(cc[h * 2] + bv, cc[h * 2 + 1] + bv);
                    *(__half2*)(ob + (long)gmm * ldOut + gc) = hv;
                }
            } else {
                __half* ob = (__half*)outp + (long)z * outBatch;
                #pragma unroll
                for (int h = 0; h < 2; ++h) {
                    int gmm = gm + h * 8;
                    float v0 = cc[h * 2], v1 = cc[h * 2 + 1];
                    if (EPI == 2) {
                        v0 = (gc     < outN) ? fmaxf(v0 + biasp[gc],     0.0f) : 0.0f;
                        v1 = (gc + 1 < outN) ? fmaxf(v1 + biasp[gc + 1], 0.0f) : 0.0f;
                    }
                    __half2 hv = __floats2half2_rn(v0, v1);
                    *(__half2*)(ob + (long)gmm * ldOut + gc) = hv;
                }
            }
        }
    }
}

// ---------------------------------------------------------------------------
// split-K reduce: out[i] = sum_z p[z][i]
// ---------------------------------------------------------------------------
__global__ __launch_bounds__(256) void reduce_split(const float4* __restrict__ p,
                                                    float4* __restrict__ out, int total4)
{
    const long stride4 = (long)M_TOK * D_IN / 4;
    for (int i = blockIdx.x * 256 + threadIdx.x; i < total4; i += gridDim.x * 256) {
        float4 a = p[i], b = p[i + stride4], c = p[i + 2 * stride4], d = p[i + 3 * stride4];
        out[i] = make_float4(a.x + b.x + c.x + d.x, a.y + b.y + c.y + d.y,
                             a.z + b.z + c.z + d.z, a.w + b.w + c.w + d.w);
    }
}

// ---------------------------------------------------------------------------
// vectorized convert fp32 -> fp16 (total % 4 == 0, pointers 16B-aligned)
// ---------------------------------------------------------------------------
__global__ __launch_bounds__(256) void convert_f16_v(const float4* __restrict__ in,
                                                     uint2* __restrict__ out, long total4)
{
    for (long i = blockIdx.x * 256L + threadIdx.x; i < total4; i += (long)gridDim.x * 256) {
        float4 v = in[i];
        __half2 h0 = __floats2half2_rn(v.x, v.y);
        __half2 h1 = __floats2half2_rn(v.z, v.w);
        uint2 pk; pk.x = *(uint32_t*)&h0; pk.y = *(uint32_t*)&h1;
        out[i] = pk;
    }
}

// ---------------------------------------------------------------------------
// row-based pad convert: fp32 in[R,C] -> fp16 out[R,Cp] (cols >= C zero).
// ---------------------------------------------------------------------------
__global__ __launch_bounds__(256) void convert_pad_row(const float* __restrict__ in,
                                                       __half* __restrict__ out,
                                                       int C, int Cp,
                                                       long inBatch, long outBatch)
{
    const int r = blockIdx.x;
    const float* irow = in  + (long)blockIdx.z * inBatch  + (long)r * C;
    __half*      orow = out + (long)blockIdx.z * outBatch + (long)r * Cp;
    for (int c2 = threadIdx.x; c2 < Cp / 2; c2 += 256) {
        int c = c2 * 2;
        float v0 = (c     < C) ? irow[c]     : 0.0f;
        float v1 = (c + 1 < C) ? irow[c + 1] : 0.0f;
        *(__half2*)(orow + c) = __floats2half2_rn(v0, v1);
    }
}

// ---------------------------------------------------------------------------
// softmax: per token m, from fp16 logits. Ch (aliases logits) [m,NP], Dh [m,NP]
// ---------------------------------------------------------------------------
__global__ __launch_bounds__(256) void softmax_kernel(const __half* __restrict__ logits,
                                                      __half* __restrict__ Ch,
                                                      __half* __restrict__ Dh)
{
    extern __shared__ float row[];
    __shared__ float red[256];
    const int m = blockIdx.x, tid = threadIdx.x;
    const __half* lrow = logits + (size_t)m * NP;

    float mx = -INFINITY;
    for (int i = tid; i < NP; i += 256) { float v = __half2float(lrow[i]); row[i] = v; mx = fmaxf(mx, v); }
    red[tid] = mx; __syncthreads();
    for (int s = 128; s > 0; s >>= 1) { if (tid < s) red[tid] = fmaxf(red[tid], red[tid + s]); __syncthreads(); }
    mx = red[0]; __syncthreads();

    float sum = 0.0f;
    for (int i = tid; i < NP; i += 256) sum += expf(row[i] - mx);
    red[tid] = sum; __syncthreads();
    for (int s = 128; s > 0; s >>= 1) { if (tid < s) red[tid] += red[tid + s]; __syncthreads(); }
    const float inv = 1.0f / red[0];

    __half* crow = Ch + (size_t)m * NP;
    for (int i = tid; i < NP; i += 256)
        crow[i] = __float2half(expf(row[i] - mx) * inv);

    __half* drow = Dh + (size_t)m * NP;
    for (int p = tid; p < P_SLOT; p += 256) {
        float l[N_EXP], mn = -INFINITY;
        #pragma unroll
        for (int n = 0; n < N_EXP; n++) { l[n] = row[n * P_SLOT + p]; mn = fmaxf(mn, l[n]); }
        float s2 = 0.0f;
        #pragma unroll
        for (int n = 0; n < N_EXP; n++) { l[n] = expf(l[n] - mn); s2 += l[n]; }
        const float inv2 = 1.0f / s2;
        #pragma unroll
        for (int n = 0; n < N_EXP; n++) drow[n * P_SLOT + p] = __float2half(l[n] * inv2);
    }
}

// ---------------------------------------------------------------------------
extern "C" void kernel_launch(void* const* d_in, const int* in_sizes, int n_in,
                              void* d_out, int out_size)
{
    const float* x   = (const float*)d_in[0];
    const float* phi = (const float*)d_in[1];
    const float* W1  = (const float*)d_in[2];
    const float* b1  = (const float*)d_in[3];
    const float* W2  = (const float*)d_in[4];
    const float* b2  = (const float*)d_in[5];
    float* out = (float*)d_out;

    __half *Ch, *Dh, *xf, *phif, *W1f, *W2f, *Xs, *H, *YsT;
    float *Yp;
    cudaGetSymbolAddress((void**)&Ch,   g_Ch);
    cudaGetSymbolAddress((void**)&Dh,   g_Dh);
    cudaGetSymbolAddress((void**)&xf,   g_xf);
    cudaGetSymbolAddress((void**)&phif, g_phif);
    cudaGetSymbolAddress((void**)&W1f,  g_W1f);
    cudaGetSymbolAddress((void**)&W2f,  g_W2f);
    cudaGetSymbolAddress((void**)&Xs,   g_Xs);
    cudaGetSymbolAddress((void**)&H,    g_H);
    cudaGetSymbolAddress((void**)&YsT,  g_YsT);
    cudaGetSymbolAddress((void**)&Yp,   g_Yp);

    cudaFuncSetAttribute(gemm_f16<1,false,true,false>,  cudaFuncAttributeMaxDynamicSharedMemorySize, SMEM_GEMM);
    cudaFuncSetAttribute(gemm_f16<1,true,true,false>,   cudaFuncAttributeMaxDynamicSharedMemorySize, SMEM_GEMM);
    cudaFuncSetAttribute(gemm_f16<2,false,true,false>,  cudaFuncAttributeMaxDynamicSharedMemorySize, SMEM_GEMM);
    cudaFuncSetAttribute(gemm_f16<4,true,false,true>,   cudaFuncAttributeMaxDynamicSharedMemorySize, SMEM_GEMM);
    cudaFuncSetAttribute(gemm_f16<0,false,false,false>, cudaFuncAttributeMaxDynamicSharedMemorySize, SMEM_GEMM);
    cudaFuncSetAttribute(softmax_kernel,                cudaFuncAttributeMaxDynamicSharedMemorySize, NP * 4);

    // side stream + fork/join events (host objects only; created once, reused —
    // captured work is identical on every call)
    static cudaStream_t sW = nullptr;
    static cudaEvent_t evFork = nullptr, evJoin = nullptr;
    if (!sW) {
        cudaStreamCreateWithFlags(&sW, cudaStreamNonBlocking);
        cudaEventCreateWithFlags(&evFork, cudaEventDisableTiming);
        cudaEventCreateWithFlags(&evJoin, cudaEventDisableTiming);
    }

    dim3 t128(128), t256(256);

    // ---- fork: weight converts on side stream (needed only at GEMM 4/5) ----
    cudaEventRecord(evFork, 0);
    cudaStreamWaitEvent(sW, evFork, 0);
    convert_f16_v<<<4096, t256, 0, sW>>>((const float4*)W2, (uint2*)W2f,
                                         (long)N_EXP * H_HID * P_SLOT / 4);
    convert_pad_row<<<dim3(D_IN, 1, N_EXP), t256, 0, sW>>>(W1, W1f, H_HID, H_PAD,
                                                           (long)D_IN * H_HID, (long)D_IN * H_PAD);
    cudaEventRecord(evJoin, sW);

    // ---- main stream: activation prep + logits/softmax/dispatch ----
    convert_f16_v<<<1024, t256>>>((const float4*)x,   (uint2*)xf,   (long)M_TOK * D_IN / 4);
    convert_f16_v<<<4096, t256>>>((const float4*)phi, (uint2*)phif, (long)D_IN * NP / 4);

    // 1) logits(fp16, into Ch) = x @ phi   (M=4096, N=16384, K=1024); B=phif MN-major
    gemm_f16<1,false,true,false><<<dim3(M_TOK/128, NP/128), t128, SMEM_GEMM>>>(
        xf, phif, nullptr, Ch, D_IN, D_IN, NP, 0,0,0,0, NP, 0, 0);

    // 2) softmaxes: Ch (in place), Dh
    softmax_kernel<<<M_TOK, t256, NP*4>>>(Ch, Ch, Dh);

    // 3) Xs = D^T @ x: A=Dh MN-major (ATR), B=xf MN-major (BTR)  (M=16384, N=1024, K=4096)
    gemm_f16<1,true,true,false><<<dim3(NP/128, D_IN/128), t128, SMEM_GEMM>>>(
        Dh, xf, nullptr, Xs, M_TOK, NP, D_IN, 0,0,0,0, D_IN, 0, 0);

    // ---- join: weights must be ready before the MLP ----
    cudaStreamWaitEvent(0, evJoin, 0);

    // 4) H = relu(Xs @ W1 + b1): B=W1f MN-major (M=1024, N=1408(pad), K=1024)
    gemm_f16<2,false,true,false><<<dim3(P_SLOT/128, H_PAD/128, N_EXP), t128, SMEM_GEMM>>>(
        Xs, W1f, b1, H, D_IN, D_IN, H_PAD,
        (long)P_SLOT*D_IN, (long)D_IN*H_PAD, H_HID, (long)P_SLOT*H_PAD, H_PAD, H_HID, 0);

    // 5) YsT[o, n*1024+p] = W2^T[o,:] . H[p,:] + b2[o]: A=W2f [h,o] (ATR, rows>=1365 zero)
    gemm_f16<4,true,false,true><<<dim3(P_SLOT/128, P_SLOT/128, N_EXP), t128, SMEM_GEMM>>>(
        W2f, H, b2, YsT, H_PAD, P_SLOT, H_PAD,
        (long)H_HID*P_SLOT, (long)P_SLOT*H_PAD, P_SLOT, P_SLOT, NP, 0, H_HID);

    // 6) Y partials = C @ Ys^T split-K=4 -> fp32 partials
    gemm_f16<0,false,false,false><<<dim3(M_TOK/128, D_IN/128, SPLITK), t128, SMEM_GEMM>>>(
        Ch, YsT, nullptr, Yp, NP/SPLITK, NP, NP,
        NP/SPLITK, NP/SPLITK, 0, (long)M_TOK*D_IN, D_IN, 0, 0);

    // 7) reduce partials -> out
    reduce_split<<<4096, t256>>>((const float4*)Yp, (float4*)out, M_TOK * D_IN / 4);

    (void)in_sizes; (void)n_in; (void)out_size;
}

// round 17
// speedup vs baseline: 1.0722x; 1.0337x over previous
#include <cuda_runtime.h>
#include <cuda_fp16.h>
#include <math.h>
#include <stdint.h>

// ---------------- problem dims ----------------
#define M_TOK 4096
#define D_IN  1024
#define N_EXP 16
#define P_SLOT 1024
#define H_HID 1365
#define H_PAD 1408
#define NP    16384
#define SPLITK 4

// ---------------- scratch ----------------
__device__ __half g_Ch  [(size_t)M_TOK*NP];           // logits then combine weights (in place)
__device__ __half g_Dh  [(size_t)M_TOK*NP];           // dispatch weights [m, np] (MN-major A)
__device__ __half g_xf  [(size_t)M_TOK*D_IN];         // x fp16 [m, d]
__device__ __half g_phif[(size_t)D_IN*NP];            // phi fp16 [d, np]  (MN-major B)
__device__ __half g_W1f [(size_t)N_EXP*D_IN*H_PAD];   // [n][d, h_pad] cols zero-padded (MN-major B)
__device__ __half g_W2f [(size_t)N_EXP*H_HID*P_SLOT]; // [n][h, o] plain fp16 (MN-major A, row-guarded)
__device__ __half g_Xs  [(size_t)NP*D_IN];            // slot inputs [np, d]
__device__ __half g_H   [(size_t)N_EXP*P_SLOT*H_PAD]; // hidden [n][p, h_pad] (pad cols zero)
__device__ __half g_YsT [(size_t)P_SLOT*NP];          // slot outputs transposed [o, np]
__device__ float  g_Yp  [(size_t)SPLITK*M_TOK*D_IN];  // combine split-K partials

// ---------------- helpers ----------------
__device__ __forceinline__ uint32_t smem_u32(const void* p) {
    return (uint32_t)__cvta_generic_to_shared(p);
}
#define SWZ(x)    ((x) ^ (((x) >> 3) & 0x70))   // 128B-row swizzle
#define SWZ256(x) ((x) ^ (((x) >> 4) & 0xF0))   // 256B-row swizzle (trans tiles)

__device__ __forceinline__ void ldsm_x4(uint32_t* r, uint32_t addr) {
    asm volatile("ldmatrix.sync.aligned.m8n8.x4.shared.b16 {%0,%1,%2,%3}, [%4];"
                 : "=r"(r[0]), "=r"(r[1]), "=r"(r[2]), "=r"(r[3]) : "r"(addr));
}
__device__ __forceinline__ void ldsm_x4_t(uint32_t* r, uint32_t addr) {
    asm volatile("ldmatrix.sync.aligned.m8n8.x4.trans.shared.b16 {%0,%1,%2,%3}, [%4];"
                 : "=r"(r[0]), "=r"(r[1]), "=r"(r[2]), "=r"(r[3]) : "r"(addr));
}
__device__ __forceinline__ void mma16816(float* c, const uint32_t* a, const uint32_t* b) {
    asm volatile("mma.sync.aligned.m16n8k16.row.col.f32.f16.f16.f32 "
        "{%0,%1,%2,%3}, {%4,%5,%6,%7}, {%8,%9}, {%0,%1,%2,%3};"
        : "+f"(c[0]), "+f"(c[1]), "+f"(c[2]), "+f"(c[3])
        : "r"(a[0]), "r"(a[1]), "r"(a[2]), "r"(a[3]), "r"(b[0]), "r"(b[1]));
}
__device__ __forceinline__ void cp16(uint32_t dst, const void* src, int srcsize) {
    asm volatile("cp.async.cg.shared.global [%0], [%1], 16, %2;"
                 :: "r"(dst), "l"(src), "r"(srcsize) : "memory");
}
#define CP_COMMIT() asm volatile("cp.async.commit_group;" ::: "memory")
#define CP_WAIT(n)  asm volatile("cp.async.wait_group %0;" :: "n"(n) : "memory")

#define STG_BYTES  32768
#define SMEM_GEMM  (2 * STG_BYTES)

// ---------------------------------------------------------------------------
// fp16 HMMA GEMM (R11 engine + register-level fragment pipelining):
//   D[128,128] = A * B^T (conceptual A[M,K], B[N,K])
//  ATR: A stored [K,M] MN-major via ldmatrix.trans (validated R11)
//  BTR: B stored [K,N] MN-major via ldmatrix.trans (validated R14)
//  ACHK: ATR rows k >= aRows read as zero (cp.async srcsize=0)
// CTA 128x128, 4 warps each 64x64, 2-stage cp.async, launch_bounds(128,2).
// Fragment double-buffering: ldsm for ks+1 issued BEFORE mma of ks.
// EPI: 0 = fp32 row-major at z*outBatch (split-K partials)
//      1 = fp16 row-major (ldOut)
//      2 = fp16 row-major + bias[col] + relu + zero cols >= outN
//      4 = fp16 row-major + bias[row], batch column offset z*outBatch
// ---------------------------------------------------------------------------
template<int EPI, bool ATR, bool BTR, bool ACHK>
__global__ __launch_bounds__(128, 2)
void gemm_f16(const __half* __restrict__ A, const __half* __restrict__ B,
              const float* __restrict__ bias, void* __restrict__ outp,
              int K, int ldA, int ldB,
              long sA, long sB, long sBias, long outBatch,
              int ldOut, int outN, int aRows)
{
    extern __shared__ char smraw[];
    const uint32_t smb = smem_u32(smraw);
    const int tid = threadIdx.x, wid = tid >> 5, lane = tid & 31;
    const int z  = blockIdx.z;
    const int m0 = blockIdx.x * 128, n0 = blockIdx.y * 128;
    A += (long)z * sA;
    B += (long)z * sB;
    const float* biasp = bias ? (bias + (long)z * sBias) : bias;

    const int nCh = K >> 6;
    const int lrow = tid >> 3;        // 0..15
    const int lj   = tid & 7;         // 16B lane within 128B row
    const int lrow2 = tid >> 4;       // 0..7   (trans tiles: 256B rows)
    const int lj2   = tid & 15;       // 16B chunk within 256B row

    auto issue = [&](int c) {
        const uint32_t smA = smb + (c & 1) * STG_BYTES;
        const uint32_t smB = smA + 16384;
        const long kb = (long)c * 64 + lj * 8;
        if (ATR) {
            #pragma unroll
            for (int i = 0; i < 8; ++i) {
                int r = lrow2 + i * 8;
                int kk = c * 64 + r;
                int ok = (!ACHK) || (kk < aRows);
                const __half* src = A + (long)(ok ? kk : 0) * ldA + (m0 + lj2 * 8);
                cp16(smA + SWZ256(r * 256 + lj2 * 16), src, ok ? 16 : 0);
            }
        } else {
            #pragma unroll
            for (int i = 0; i < 8; ++i) {
                int r = lrow + i * 16;
                cp16(smA + SWZ(r * 128 + lj * 16), A + (long)(m0 + r) * ldA + kb, 16);
            }
        }
        if (BTR) {
            #pragma unroll
            for (int i = 0; i < 8; ++i) {
                int r = lrow2 + i * 8;
                cp16(smB + SWZ256(r * 256 + lj2 * 16),
                     B + (long)(c * 64 + r) * ldB + (n0 + lj2 * 8), 16);
            }
        } else {
            #pragma unroll
            for (int i = 0; i < 8; ++i) {
                int r = lrow + i * 16;
                cp16(smB + SWZ(r * 128 + lj * 16), B + (long)(n0 + r) * ldB + kb, 16);
            }
        }
        CP_COMMIT();
    };

    float acc[4][8][4] = {};
    const int wm = (wid >> 1) * 64;
    const int wn = (wid & 1) * 64;

    // fragment double buffers
    uint32_t af[2][4][4], bf[2][8][2];

    auto load_frags = [&](uint32_t smA, uint32_t smB, int ks, int buf) {
        const int kb = ks * 32;
        if (ATR) {
            const int krow = ks * 16 + (lane & 7) + ((lane >> 4) << 3);
            const int msub = ((lane >> 3) & 1) << 3;
            #pragma unroll
            for (int mb = 0; mb < 4; ++mb) {
                int mcol = wm + mb * 16 + msub;
                ldsm_x4_t(af[buf][mb], smA + SWZ256(krow * 256 + mcol * 2));
            }
        } else {
            #pragma unroll
            for (int mb = 0; mb < 4; ++mb) {
                int row = wm + mb * 16 + (lane & 15);
                ldsm_x4(af[buf][mb], smA + SWZ(row * 128 + kb + ((lane >> 4) << 4)));
            }
        }
        if (BTR) {
            const int krow = ks * 16 + (lane & 7) + (((lane >> 3) & 1) << 3);
            const int nsub = (lane >> 4) << 3;
            #pragma unroll
            for (int npair = 0; npair < 4; ++npair) {
                int ncol = wn + npair * 16 + nsub;
                uint32_t r4[4];
                ldsm_x4_t(r4, smB + SWZ256(krow * 256 + ncol * 2));
                bf[buf][npair*2  ][0] = r4[0]; bf[buf][npair*2  ][1] = r4[1];
                bf[buf][npair*2+1][0] = r4[2]; bf[buf][npair*2+1][1] = r4[3];
            }
        } else {
            #pragma unroll
            for (int npair = 0; npair < 4; ++npair) {
                int row = wn + npair * 16 + (lane & 7) + ((lane >> 4) << 3);
                uint32_t r4[4];
                ldsm_x4(r4, smB + SWZ(row * 128 + kb + (((lane >> 3) & 1) << 4)));
                bf[buf][npair*2  ][0] = r4[0]; bf[buf][npair*2  ][1] = r4[1];
                bf[buf][npair*2+1][0] = r4[2]; bf[buf][npair*2+1][1] = r4[3];
            }
        }
    };

    issue(0);

    for (int c = 0; c < nCh; ++c) {
        if (c + 1 < nCh) { issue(c + 1); CP_WAIT(1); } else { CP_WAIT(0); }
        __syncthreads();

        const uint32_t smA = smb + (c & 1) * STG_BYTES;
        const uint32_t smB = smA + 16384;

        load_frags(smA, smB, 0, 0);
        #pragma unroll
        for (int ks = 0; ks < 4; ++ks) {
            const int cur = ks & 1;
            if (ks < 3) load_frags(smA, smB, ks + 1, cur ^ 1);
            #pragma unroll
            for (int mb = 0; mb < 4; ++mb)
                #pragma unroll
                for (int nb = 0; nb < 8; ++nb)
                    mma16816(acc[mb][nb], af[cur][mb], bf[cur][nb]);
        }
        __syncthreads();
    }

    // ---------------- epilogue ----------------
    const int erow = lane >> 2;
    const int ecol = (lane & 3) * 2;
    #pragma unroll
    for (int mb = 0; mb < 4; ++mb) {
        #pragma unroll
        for (int nb = 0; nb < 8; ++nb) {
            float* cc = acc[mb][nb];
            const int gm = m0 + wm + mb * 16 + erow;
            const int gc = n0 + wn + nb * 8 + ecol;
            if (EPI == 0) {
                float* ob = (float*)outp + (long)z * outBatch;
                *(float2*)(ob + (long)gm * ldOut + gc)       = make_float2(cc[0], cc[1]);
                *(float2*)(ob + (long)(gm + 8) * ldOut + gc) = make_float2(cc[2], cc[3]);
            } else if (EPI == 4) {
                __half* ob = (__half*)outp + (long)z * outBatch;
                #pragma unroll
                for (int h = 0; h < 2; ++h) {
                    int gmm = gm + h * 8;
                    float bv = biasp[gmm];
                    __half2 hv = __floats2half2_rn(cc[h * 2] + bv, cc[h * 2 + 1] + bv);
                    *(__half2*)(ob + (long)gmm * ldOut + gc) = hv;
                }
            } else {
                __half* ob = (__half*)outp + (long)z * outBatch;
                #pragma unroll
                for (int h = 0; h < 2; ++h) {
                    int gmm = gm + h * 8;
                    float v0 = cc[h * 2], v1 = cc[h * 2 + 1];
                    if (EPI == 2) {
                        v0 = (gc     < outN) ? fmaxf(v0 + biasp[gc],     0.0f) : 0.0f;
                        v1 = (gc + 1 < outN) ? fmaxf(v1 + biasp[gc + 1], 0.0f) : 0.0f;
                    }
                    __half2 hv = __floats2half2_rn(v0, v1);
                    *(__half2*)(ob + (long)gmm * ldOut + gc) = hv;
                }
            }
        }
    }
}

// ---------------------------------------------------------------------------
// split-K reduce: out[i] = sum_z p[z][i]
// ---------------------------------------------------------------------------
__global__ __launch_bounds__(256) void reduce_split(const float4* __restrict__ p,
                                                    float4* __restrict__ out, int total4)
{
    const long stride4 = (long)M_TOK * D_IN / 4;
    for (int i = blockIdx.x * 256 + threadIdx.x; i < total4; i += gridDim.x * 256) {
        float4 a = p[i], b = p[i + stride4], c = p[i + 2 * stride4], d = p[i + 3 * stride4];
        out[i] = make_float4(a.x + b.x + c.x + d.x, a.y + b.y + c.y + d.y,
                             a.z + b.z + c.z + d.z, a.w + b.w + c.w + d.w);
    }
}

// ---------------------------------------------------------------------------
// vectorized convert fp32 -> fp16
// ---------------------------------------------------------------------------
__global__ __launch_bounds__(256) void convert_f16_v(const float4* __restrict__ in,
                                                     uint2* __restrict__ out, long total4)
{
    for (long i = blockIdx.x * 256L + threadIdx.x; i < total4; i += (long)gridDim.x * 256) {
        float4 v = in[i];
        __half2 h0 = __floats2half2_rn(v.x, v.y);
        __half2 h1 = __floats2half2_rn(v.z, v.w);
        uint2 pk; pk.x = *(uint32_t*)&h0; pk.y = *(uint32_t*)&h1;
        out[i] = pk;
    }
}

// ---------------------------------------------------------------------------
// row-based pad convert: fp32 in[R,C] -> fp16 out[R,Cp] (cols >= C zero).
// ---------------------------------------------------------------------------
__global__ __launch_bounds__(256) void convert_pad_row(const float* __restrict__ in,
                                                       __half* __restrict__ out,
                                                       int C, int Cp,
                                                       long inBatch, long outBatch)
{
    const int r = blockIdx.x;
    const float* irow = in  + (long)blockIdx.z * inBatch  + (long)r * C;
    __half*      orow = out + (long)blockIdx.z * outBatch + (long)r * Cp;
    for (int c2 = threadIdx.x; c2 < Cp / 2; c2 += 256) {
        int c = c2 * 2;
        float v0 = (c     < C) ? irow[c]     : 0.0f;
        float v1 = (c + 1 < C) ? irow[c + 1] : 0.0f;
        *(__half2*)(orow + c) = __floats2half2_rn(v0, v1);
    }
}

// ---------------------------------------------------------------------------
// softmax: per token m, from fp16 logits. Ch (aliases logits) [m,NP], Dh [m,NP]
// ---------------------------------------------------------------------------
__global__ __launch_bounds__(256) void softmax_kernel(const __half* __restrict__ logits,
                                                      __half* __restrict__ Ch,
                                                      __half* __restrict__ Dh)
{
    extern __shared__ float row[];
    __shared__ float red[256];
    const int m = blockIdx.x, tid = threadIdx.x;
    const __half* lrow = logits + (size_t)m * NP;

    float mx = -INFINITY;
    for (int i = tid; i < NP; i += 256) { float v = __half2float(lrow[i]); row[i] = v; mx = fmaxf(mx, v); }
    red[tid] = mx; __syncthreads();
    for (int s = 128; s > 0; s >>= 1) { if (tid < s) red[tid] = fmaxf(red[tid], red[tid + s]); __syncthreads(); }
    mx = red[0]; __syncthreads();

    float sum = 0.0f;
    for (int i = tid; i < NP; i += 256) sum += expf(row[i] - mx);
    red[tid] = sum; __syncthreads();
    for (int s = 128; s > 0; s >>= 1) { if (tid < s) red[tid] += red[tid + s]; __syncthreads(); }
    const float inv = 1.0f / red[0];

    __half* crow = Ch + (size_t)m * NP;
    for (int i = tid; i < NP; i += 256)
        crow[i] = __float2half(expf(row[i] - mx) * inv);

    __half* drow = Dh + (size_t)m * NP;
    for (int p = tid; p < P_SLOT; p += 256) {
        float l[N_EXP], mn = -INFINITY;
        #pragma unroll
        for (int n = 0; n < N_EXP; n++) { l[n] = row[n * P_SLOT + p]; mn = fmaxf(mn, l[n]); }
        float s2 = 0.0f;
        #pragma unroll
        for (int n = 0; n < N_EXP; n++) { l[n] = expf(l[n] - mn); s2 += l[n]; }
        const float inv2 = 1.0f / s2;
        #pragma unroll
        for (int n = 0; n < N_EXP; n++) drow[n * P_SLOT + p] = __float2half(l[n] * inv2);
    }
}

// ---------------------------------------------------------------------------
extern "C" void kernel_launch(void* const* d_in, const int* in_sizes, int n_in,
                              void* d_out, int out_size)
{
    const float* x   = (const float*)d_in[0];
    const float* phi = (const float*)d_in[1];
    const float* W1  = (const float*)d_in[2];
    const float* b1  = (const float*)d_in[3];
    const float* W2  = (const float*)d_in[4];
    const float* b2  = (const float*)d_in[5];
    float* out = (float*)d_out;

    __half *Ch, *Dh, *xf, *phif, *W1f, *W2f, *Xs, *H, *YsT;
    float *Yp;
    cudaGetSymbolAddress((void**)&Ch,   g_Ch);
    cudaGetSymbolAddress((void**)&Dh,   g_Dh);
    cudaGetSymbolAddress((void**)&xf,   g_xf);
    cudaGetSymbolAddress((void**)&phif, g_phif);
    cudaGetSymbolAddress((void**)&W1f,  g_W1f);
    cudaGetSymbolAddress((void**)&W2f,  g_W2f);
    cudaGetSymbolAddress((void**)&Xs,   g_Xs);
    cudaGetSymbolAddress((void**)&H,    g_H);
    cudaGetSymbolAddress((void**)&YsT,  g_YsT);
    cudaGetSymbolAddress((void**)&Yp,   g_Yp);

    cudaFuncSetAttribute(gemm_f16<1,false,true,false>,  cudaFuncAttributeMaxDynamicSharedMemorySize, SMEM_GEMM);
    cudaFuncSetAttribute(gemm_f16<1,true,true,false>,   cudaFuncAttributeMaxDynamicSharedMemorySize, SMEM_GEMM);
    cudaFuncSetAttribute(gemm_f16<2,false,true,false>,  cudaFuncAttributeMaxDynamicSharedMemorySize, SMEM_GEMM);
    cudaFuncSetAttribute(gemm_f16<4,true,false,true>,   cudaFuncAttributeMaxDynamicSharedMemorySize, SMEM_GEMM);
    cudaFuncSetAttribute(gemm_f16<0,false,false,false>, cudaFuncAttributeMaxDynamicSharedMemorySize, SMEM_GEMM);
    cudaFuncSetAttribute(softmax_kernel,                cudaFuncAttributeMaxDynamicSharedMemorySize, NP * 4);

    static cudaStream_t sW = nullptr;
    static cudaEvent_t evFork = nullptr, evJoin = nullptr;
    if (!sW) {
        cudaStreamCreateWithFlags(&sW, cudaStreamNonBlocking);
        cudaEventCreateWithFlags(&evFork, cudaEventDisableTiming);
        cudaEventCreateWithFlags(&evJoin, cudaEventDisableTiming);
    }

    dim3 t128(128), t256(256);

    // ---- fork: weight converts on side stream ----
    cudaEventRecord(evFork, 0);
    cudaStreamWaitEvent(sW, evFork, 0);
    convert_f16_v<<<4096, t256, 0, sW>>>((const float4*)W2, (uint2*)W2f,
                                         (long)N_EXP * H_HID * P_SLOT / 4);
    convert_pad_row<<<dim3(D_IN, 1, N_EXP), t256, 0, sW>>>(W1, W1f, H_HID, H_PAD,
                                                           (long)D_IN * H_HID, (long)D_IN * H_PAD);
    cudaEventRecord(evJoin, sW);

    // ---- main stream ----
    convert_f16_v<<<1024, t256>>>((const float4*)x,   (uint2*)xf,   (long)M_TOK * D_IN / 4);
    convert_f16_v<<<4096, t256>>>((const float4*)phi, (uint2*)phif, (long)D_IN * NP / 4);

    // 1) logits(fp16, into Ch) = x @ phi   (M=4096, N=16384, K=1024); B=phif MN-major
    gemm_f16<1,false,true,false><<<dim3(M_TOK/128, NP/128), t128, SMEM_GEMM>>>(
        xf, phif, nullptr, Ch, D_IN, D_IN, NP, 0,0,0,0, NP, 0, 0);

    // 2) softmaxes: Ch (in place), Dh
    softmax_kernel<<<M_TOK, t256, NP*4>>>(Ch, Ch, Dh);

    // 3) Xs = D^T @ x: A=Dh MN-major (ATR), B=xf MN-major (BTR)
    gemm_f16<1,true,true,false><<<dim3(NP/128, D_IN/128), t128, SMEM_GEMM>>>(
        Dh, xf, nullptr, Xs, M_TOK, NP, D_IN, 0,0,0,0, D_IN, 0, 0);

    // ---- join: weights ready before the MLP ----
    cudaStreamWaitEvent(0, evJoin, 0);

    // 4) H = relu(Xs @ W1 + b1): B=W1f MN-major
    gemm_f16<2,false,true,false><<<dim3(P_SLOT/128, H_PAD/128, N_EXP), t128, SMEM_GEMM>>>(
        Xs, W1f, b1, H, D_IN, D_IN, H_PAD,
        (long)P_SLOT*D_IN, (long)D_IN*H_PAD, H_HID, (long)P_SLOT*H_PAD, H_PAD, H_HID, 0);

    // 5) YsT = W2^T @ H^T + b2: A=W2f [h,o] (ATR, rows>=1365 zero)
    gemm_f16<4,true,false,true><<<dim3(P_SLOT/128, P_SLOT/128, N_EXP), t128, SMEM_GEMM>>>(
        W2f, H, b2, YsT, H_PAD, P_SLOT, H_PAD,
        (long)H_HID*P_SLOT, (long)P_SLOT*H_PAD, P_SLOT, P_SLOT, NP, 0, H_HID);

    // 6) Y partials = C @ Ys^T split-K=4
    gemm_f16<0,false,false,false><<<dim3(M_TOK/128, D_IN/128, SPLITK), t128, SMEM_GEMM>>>(
        Ch, YsT, nullptr, Yp, NP/SPLITK, NP, NP,
        NP/SPLITK, NP/SPLITK, 0, (long)M_TOK*D_IN, D_IN, 0, 0);

    // 7) reduce partials -> out
    reduce_split<<<4096, t256>>>((const float4*)Yp, (float4*)out, M_TOK * D_IN / 4);

    (void)in_sizes; (void)n_in; (void)out_size;
}